// round 1
// baseline (speedup 1.0000x reference)
#include <cuda_runtime.h>
#include <math.h>

// Problem constants
#define NN 8192
#define DD 512
#define EPS_INV 5.0f            // epsilon = 0.1*2 = 0.2 ; log_K = -C/eps = -5*C
#define NEGBIG (-3.0e38f)

// ---------------- device scratch (static: allocation rules) ----------------
__device__ float g_X[NN * DD];              // normalized embeddings   16 MB
__device__ float g_Y[NN * DD];              // normalized target noise 16 MB
__device__ float g_sqx[NN];
__device__ float g_sqy[NN];
__device__ float g_C[(size_t)NN * (size_t)NN];  // cost matrix, 256 MB
__device__ float g_logu[NN];
__device__ float g_logv[NN];
__device__ float g_cm[32 * NN];             // column partial maxes
__device__ float g_cs[32 * NN];             // column partial scaled sums
__device__ float g_accum;                   // sum(P*C)
__device__ float g_fb;                      // sum of row dots (fallback)

// ---------------- init ----------------
__global__ void init_kernel() {
    int i = blockIdx.x * blockDim.x + threadIdx.x;
    if (i < NN) { g_logu[i] = 0.f; g_logv[i] = 0.f; }
    if (i == 0) { g_accum = 0.f; g_fb = 0.f; }
}

// ---------------- normalize: one block per row (X rows then Y rows) --------
__global__ __launch_bounds__(128) void normalize_kernel(const float* __restrict__ emb,
                                                        const float* __restrict__ tn) {
    int b = blockIdx.x;
    const float* src;
    float* dst;
    float* sqv;
    int row;
    if (b < NN) { row = b;      src = emb + (size_t)row * DD; dst = g_X + (size_t)row * DD; sqv = g_sqx; }
    else        { row = b - NN; src = tn  + (size_t)row * DD; dst = g_Y + (size_t)row * DD; sqv = g_sqy; }

    int tid = threadIdx.x;
    float4 v = ((const float4*)src)[tid];           // 128 threads * 4 = 512
    float ss = v.x*v.x + v.y*v.y + v.z*v.z + v.w*v.w;

    __shared__ float red[4];
    #pragma unroll
    for (int o = 16; o > 0; o >>= 1) ss += __shfl_xor_sync(0xffffffffu, ss, o);
    if ((tid & 31) == 0) red[tid >> 5] = ss;
    __syncthreads();
    float tot = red[0] + red[1] + red[2] + red[3];

    float norm = sqrtf(tot);
    float inv  = 1.0f / fmaxf(norm, 1e-12f);
    float4 w;
    w.x = v.x * inv; w.y = v.y * inv; w.z = v.z * inv; w.w = v.w * inv;
    ((float4*)dst)[tid] = w;

    // sq of the (rounded) normalized values, matching the reference
    float ss2 = w.x*w.x + w.y*w.y + w.z*w.z + w.w*w.w;
    #pragma unroll
    for (int o = 16; o > 0; o >>= 1) ss2 += __shfl_xor_sync(0xffffffffu, ss2, o);
    __syncthreads();
    if ((tid & 31) == 0) red[tid >> 5] = ss2;
    __syncthreads();
    if (tid == 0) sqv[row] = red[0] + red[1] + red[2] + red[3];
}

// ---------------- GEMM: C = max(sqx_i + sqy_j - 2 * X Y^T, 0) -------------
// 128x128 tile, BK=8, 256 threads, 8x8 per thread.
__global__ __launch_bounds__(256) void gemm_kernel() {
    __shared__ float As[8][128];
    __shared__ float Bs[8][128];

    int tid = threadIdx.x;
    int tx = tid & 15;          // 0..15  -> column group
    int ty = tid >> 4;          // 0..15  -> row group
    int brow = blockIdx.y * 128;
    int bcol = blockIdx.x * 128;

    float acc[8][8];
    #pragma unroll
    for (int i = 0; i < 8; i++)
        #pragma unroll
        for (int j = 0; j < 8; j++) acc[i][j] = 0.f;

    // global load mapping: 1024 floats per tile = 256 float4
    int lrow = tid >> 1;          // 0..127
    int lk4  = (tid & 1) * 4;     // 0 or 4
    const float* Xp = g_X + (size_t)(brow + lrow) * DD + lk4;
    const float* Yp = g_Y + (size_t)(bcol + lrow) * DD + lk4;

    for (int k0 = 0; k0 < DD; k0 += 8) {
        float4 av = *(const float4*)(Xp + k0);
        float4 bv = *(const float4*)(Yp + k0);
        As[lk4 + 0][lrow] = av.x; As[lk4 + 1][lrow] = av.y;
        As[lk4 + 2][lrow] = av.z; As[lk4 + 3][lrow] = av.w;
        Bs[lk4 + 0][lrow] = bv.x; Bs[lk4 + 1][lrow] = bv.y;
        Bs[lk4 + 2][lrow] = bv.z; Bs[lk4 + 3][lrow] = bv.w;
        __syncthreads();

        #pragma unroll
        for (int k = 0; k < 8; k++) {
            float a[8], b[8];
            #pragma unroll
            for (int i = 0; i < 8; i++) a[i] = As[k][ty * 8 + i];
            #pragma unroll
            for (int j = 0; j < 8; j++) b[j] = Bs[k][tx * 8 + j];
            #pragma unroll
            for (int i = 0; i < 8; i++)
                #pragma unroll
                for (int j = 0; j < 8; j++)
                    acc[i][j] = fmaf(a[i], b[j], acc[i][j]);
        }
        __syncthreads();
    }

    // epilogue
    float srow[8], scol[8];
    #pragma unroll
    for (int i = 0; i < 8; i++) srow[i] = g_sqx[brow + ty * 8 + i];
    #pragma unroll
    for (int j = 0; j < 8; j++) scol[j] = g_sqy[bcol + tx * 8 + j];

    #pragma unroll
    for (int i = 0; i < 8; i++) {
        size_t base = (size_t)(brow + ty * 8 + i) * NN + (bcol + tx * 8);
        float4 o0, o1;
        o0.x = fmaxf(srow[i] + scol[0] - 2.f * acc[i][0], 0.f);
        o0.y = fmaxf(srow[i] + scol[1] - 2.f * acc[i][1], 0.f);
        o0.z = fmaxf(srow[i] + scol[2] - 2.f * acc[i][2], 0.f);
        o0.w = fmaxf(srow[i] + scol[3] - 2.f * acc[i][3], 0.f);
        o1.x = fmaxf(srow[i] + scol[4] - 2.f * acc[i][4], 0.f);
        o1.y = fmaxf(srow[i] + scol[5] - 2.f * acc[i][5], 0.f);
        o1.z = fmaxf(srow[i] + scol[6] - 2.f * acc[i][6], 0.f);
        o1.w = fmaxf(srow[i] + scol[7] - 2.f * acc[i][7], 0.f);
        *(float4*)(g_C + base)     = o0;
        *(float4*)(g_C + base + 4) = o1;
    }
}

// ---------------- fallback: sum of row dot products of normalized x,y ------
__global__ __launch_bounds__(128) void fallback_kernel() {
    int row = blockIdx.x;
    int tid = threadIdx.x;
    float4 x = ((const float4*)(g_X + (size_t)row * DD))[tid];
    float4 y = ((const float4*)(g_Y + (size_t)row * DD))[tid];
    float d = x.x*y.x + x.y*y.y + x.z*y.z + x.w*y.w;
    __shared__ float red[4];
    #pragma unroll
    for (int o = 16; o > 0; o >>= 1) d += __shfl_xor_sync(0xffffffffu, d, o);
    if ((tid & 31) == 0) red[tid >> 5] = d;
    __syncthreads();
    if (tid == 0) atomicAdd(&g_fb, red[0] + red[1] + red[2] + red[3]);
}

// ---------------- row pass: log_u_i = -LSE_j(-5*C_ij + log_v_j) ------------
__global__ __launch_bounds__(256) void row_lse_kernel() {
    int row = blockIdx.x;
    int tid = threadIdx.x;
    const float4* Cr = (const float4*)(g_C + (size_t)row * NN);
    const float4* Lv = (const float4*)g_logv;

    float m = NEGBIG, s = 0.f;
    for (int c = tid; c < NN / 4; c += 256) {
        float4 cv = Cr[c];
        float4 lv = Lv[c];
        float a;
        a = fmaf(-EPS_INV, cv.x, lv.x);
        if (a > m) { s = s * expf(m - a) + 1.f; m = a; } else s += expf(a - m);
        a = fmaf(-EPS_INV, cv.y, lv.y);
        if (a > m) { s = s * expf(m - a) + 1.f; m = a; } else s += expf(a - m);
        a = fmaf(-EPS_INV, cv.z, lv.z);
        if (a > m) { s = s * expf(m - a) + 1.f; m = a; } else s += expf(a - m);
        a = fmaf(-EPS_INV, cv.w, lv.w);
        if (a > m) { s = s * expf(m - a) + 1.f; m = a; } else s += expf(a - m);
    }

    __shared__ float sm[256], ss[256];
    sm[tid] = m; ss[tid] = s;
    __syncthreads();
    for (int o = 128; o > 0; o >>= 1) {
        if (tid < o) {
            float m1 = sm[tid], s1 = ss[tid];
            float m2 = sm[tid + o], s2 = ss[tid + o];
            float M = fmaxf(m1, m2);
            sm[tid] = M;
            ss[tid] = s1 * expf(m1 - M) + s2 * expf(m2 - M);
        }
        __syncthreads();
    }
    if (tid == 0) g_logu[row] = -(sm[0] + logf(ss[0]));
}

// ------------- column pass, phase 1: per (row-chunk, column) partial LSE ---
// grid (32 row-chunks, 32 col-blocks), 256 threads; thread owns one column.
__global__ __launch_bounds__(256) void col_partial_kernel() {
    int col = blockIdx.y * 256 + threadIdx.x;
    int r0  = blockIdx.x * 256;
    __shared__ float slu[256];
    slu[threadIdx.x] = g_logu[r0 + threadIdx.x];
    __syncthreads();

    float m = NEGBIG, s = 0.f;
    const float* Cp = g_C + (size_t)r0 * NN + col;
    #pragma unroll 4
    for (int i = 0; i < 256; i++) {
        float a = fmaf(-EPS_INV, Cp[(size_t)i * NN], slu[i]);
        if (a > m) { s = s * expf(m - a) + 1.f; m = a; } else s += expf(a - m);
    }
    g_cm[blockIdx.x * NN + col] = m;
    g_cs[blockIdx.x * NN + col] = s;
}

// ------------- column pass, phase 2: combine 32 partials per column --------
__global__ __launch_bounds__(256) void col_combine_kernel() {
    int col = blockIdx.x * 256 + threadIdx.x;
    float M = NEGBIG;
    #pragma unroll
    for (int ch = 0; ch < 32; ch++) M = fmaxf(M, g_cm[ch * NN + col]);
    float S = 0.f;
    #pragma unroll
    for (int ch = 0; ch < 32; ch++) S += g_cs[ch * NN + col] * expf(g_cm[ch * NN + col] - M);
    g_logv[col] = -(M + logf(S));
}

// ------------- final: sum over all i,j of clip(exp(lu+lK+lv),0,1) * C ------
__global__ __launch_bounds__(256) void distance_kernel() {
    int row = blockIdx.x;
    int tid = threadIdx.x;
    float lu = g_logu[row];
    const float4* Cr = (const float4*)(g_C + (size_t)row * NN);
    const float4* Lv = (const float4*)g_logv;

    float sum = 0.f;
    for (int c = tid; c < NN / 4; c += 256) {
        float4 cv = Cr[c];
        float4 lv = Lv[c];
        float p;
        p = expf(fmaf(-EPS_INV, cv.x, lu + lv.x)); p = fminf(p, 1.f); sum = fmaf(p, cv.x, sum);
        p = expf(fmaf(-EPS_INV, cv.y, lu + lv.y)); p = fminf(p, 1.f); sum = fmaf(p, cv.y, sum);
        p = expf(fmaf(-EPS_INV, cv.z, lu + lv.z)); p = fminf(p, 1.f); sum = fmaf(p, cv.z, sum);
        p = expf(fmaf(-EPS_INV, cv.w, lu + lv.w)); p = fminf(p, 1.f); sum = fmaf(p, cv.w, sum);
    }

    __shared__ float red[8];
    #pragma unroll
    for (int o = 16; o > 0; o >>= 1) sum += __shfl_xor_sync(0xffffffffu, sum, o);
    if ((tid & 31) == 0) red[tid >> 5] = sum;
    __syncthreads();
    if (tid == 0) {
        float b = 0.f;
        #pragma unroll
        for (int w = 0; w < 8; w++) b += red[w];
        atomicAdd(&g_accum, b);
    }
}

// ---------------- finalize ----------------
__global__ void finalize_kernel(float* out) {
    float d  = g_accum / (float)NN;
    float fb = 1.f - g_fb / (float)NN;
    out[0] = (isnan(d) || isinf(d)) ? fb : d;
}

// ---------------- launch ----------------
extern "C" void kernel_launch(void* const* d_in, const int* in_sizes, int n_in,
                              void* d_out, int out_size) {
    const float* emb = (const float*)d_in[0];
    const float* tn  = (const float*)d_in[1];
    float* out = (float*)d_out;

    init_kernel<<<32, 256>>>();
    normalize_kernel<<<2 * NN, 128>>>(emb, tn);
    gemm_kernel<<<dim3(64, 64), 256>>>();
    fallback_kernel<<<NN, 128>>>();

    for (int it = 0; it < 10; it++) {
        row_lse_kernel<<<NN, 256>>>();
        col_partial_kernel<<<dim3(32, 32), 256>>>();
        col_combine_kernel<<<32, 256>>>();
    }

    distance_kernel<<<NN, 256>>>();
    finalize_kernel<<<1, 1>>>(out);
}

// round 3
// speedup vs baseline: 1.4162x; 1.4162x over previous
#include <cuda_runtime.h>
#include <cuda_bf16.h>
#include <math.h>
#include <stdint.h>

// Problem constants
#define NN 8192
#define DD 512
#define KK 1536                  // split-bf16: [hi|hi|lo] x [hi|lo|hi]
#define EPS_INV 5.0f             // epsilon = 0.1*2 = 0.2 ; log_K = -C/eps = -5*C
#define NEGBIG (-3.0e38f)

// ---------------- device scratch (static: allocation rules) ----------------
__device__ float g_X[NN * DD];              // normalized embeddings   16 MB
__device__ float g_Y[NN * DD];              // normalized target noise 16 MB
__device__ __nv_bfloat16 g_Xs[(size_t)NN * KK];  // A = [x_hi | x_hi | x_lo]  24 MB
__device__ __nv_bfloat16 g_Ys[(size_t)NN * KK];  // B = [y_hi | y_lo | y_hi]  24 MB
__device__ float g_sqx[NN];
__device__ float g_sqy[NN];
__device__ float g_C[(size_t)NN * (size_t)NN];  // cost matrix, 256 MB
__device__ float g_logu[NN];
__device__ float g_logv[NN];
__device__ float g_cm[32 * NN];             // column partial maxes
__device__ float g_cs[32 * NN];             // column partial scaled sums
__device__ float g_accum;                   // sum(P*C)
__device__ float g_fb;                      // sum of row dots (fallback)

// ---------------- helpers ----------------
__device__ __forceinline__ uint32_t smem_u32(const void* p) {
    uint32_t a;
    asm("{ .reg .u64 t; cvta.to.shared.u64 t, %1; cvt.u32.u64 %0, t; }" : "=r"(a) : "l"(p));
    return a;
}
__device__ __forceinline__ void cp_async16(uint32_t s, const void* g) {
    asm volatile("cp.async.cg.shared.global [%0], [%1], 16;" :: "r"(s), "l"(g));
}
#define CP_COMMIT()  asm volatile("cp.async.commit_group;" ::: "memory")
#define CP_WAIT(n)   asm volatile("cp.async.wait_group %0;" :: "n"(n) : "memory")

__device__ __forceinline__ void ldmatrix_x4(uint32_t& r0, uint32_t& r1, uint32_t& r2, uint32_t& r3,
                                            uint32_t addr) {
    asm volatile("ldmatrix.sync.aligned.m8n8.x4.shared.b16 {%0,%1,%2,%3}, [%4];"
                 : "=r"(r0), "=r"(r1), "=r"(r2), "=r"(r3) : "r"(addr));
}
__device__ __forceinline__ void mma_16816(float* c, const uint32_t* a, const uint32_t* b) {
    asm volatile("mma.sync.aligned.m16n8k16.row.col.f32.bf16.bf16.f32 "
                 "{%0,%1,%2,%3}, {%4,%5,%6,%7}, {%8,%9}, {%0,%1,%2,%3};"
                 : "+f"(c[0]), "+f"(c[1]), "+f"(c[2]), "+f"(c[3])
                 : "r"(a[0]), "r"(a[1]), "r"(a[2]), "r"(a[3]), "r"(b[0]), "r"(b[1]));
}

// ---------------- init ----------------
__global__ void init_kernel() {
    int i = blockIdx.x * blockDim.x + threadIdx.x;
    if (i < NN) { g_logu[i] = 0.f; g_logv[i] = 0.f; }
    if (i == 0) { g_accum = 0.f; g_fb = 0.f; }
}

// ---------------- normalize + build bf16 split operands ----------------
__global__ __launch_bounds__(128) void normalize_kernel(const float* __restrict__ emb,
                                                        const float* __restrict__ tn) {
    int b = blockIdx.x;
    const float* src;
    float* dst;
    float* sqv;
    __nv_bfloat16* split;
    int is_x;
    int row;
    if (b < NN) { row = b;      src = emb + (size_t)row * DD; dst = g_X + (size_t)row * DD; sqv = g_sqx; split = g_Xs + (size_t)row * KK; is_x = 1; }
    else        { row = b - NN; src = tn  + (size_t)row * DD; dst = g_Y + (size_t)row * DD; sqv = g_sqy; split = g_Ys + (size_t)row * KK; is_x = 0; }

    int tid = threadIdx.x;
    float4 v = ((const float4*)src)[tid];
    float ss = v.x*v.x + v.y*v.y + v.z*v.z + v.w*v.w;

    __shared__ float red[4];
    #pragma unroll
    for (int o = 16; o > 0; o >>= 1) ss += __shfl_xor_sync(0xffffffffu, ss, o);
    if ((tid & 31) == 0) red[tid >> 5] = ss;
    __syncthreads();
    float tot = red[0] + red[1] + red[2] + red[3];

    float norm = sqrtf(tot);
    float inv  = 1.0f / fmaxf(norm, 1e-12f);
    float4 w;
    w.x = v.x * inv; w.y = v.y * inv; w.z = v.z * inv; w.w = v.w * inv;
    ((float4*)dst)[tid] = w;

    // bf16 hi/lo split
    __nv_bfloat16 hx = __float2bfloat16(w.x), hy = __float2bfloat16(w.y);
    __nv_bfloat16 hz = __float2bfloat16(w.z), hw = __float2bfloat16(w.w);
    __nv_bfloat16 lx = __float2bfloat16(w.x - __bfloat162float(hx));
    __nv_bfloat16 ly = __float2bfloat16(w.y - __bfloat162float(hy));
    __nv_bfloat16 lz = __float2bfloat16(w.z - __bfloat162float(hz));
    __nv_bfloat16 lw = __float2bfloat16(w.w - __bfloat162float(hw));

    uint32_t hi01 = (uint32_t)__bfloat16_as_ushort(hx) | ((uint32_t)__bfloat16_as_ushort(hy) << 16);
    uint32_t hi23 = (uint32_t)__bfloat16_as_ushort(hz) | ((uint32_t)__bfloat16_as_ushort(hw) << 16);
    uint32_t lo01 = (uint32_t)__bfloat16_as_ushort(lx) | ((uint32_t)__bfloat16_as_ushort(ly) << 16);
    uint32_t lo23 = (uint32_t)__bfloat16_as_ushort(lz) | ((uint32_t)__bfloat16_as_ushort(lw) << 16);

    int k = tid * 4;
    uint2 hi_pack = make_uint2(hi01, hi23);
    uint2 lo_pack = make_uint2(lo01, lo23);
    *(uint2*)(split + k) = hi_pack;            // segment 0: hi (both)
    if (is_x) {                                // A = [hi | hi | lo]
        *(uint2*)(split + k + DD)   = hi_pack;
        *(uint2*)(split + k + 2*DD) = lo_pack;
    } else {                                   // B = [hi | lo | hi]
        *(uint2*)(split + k + DD)   = lo_pack;
        *(uint2*)(split + k + 2*DD) = hi_pack;
    }

    float ss2 = w.x*w.x + w.y*w.y + w.z*w.z + w.w*w.w;
    #pragma unroll
    for (int o = 16; o > 0; o >>= 1) ss2 += __shfl_xor_sync(0xffffffffu, ss2, o);
    __syncthreads();
    if ((tid & 31) == 0) red[tid >> 5] = ss2;
    __syncthreads();
    if (tid == 0) sqv[row] = red[0] + red[1] + red[2] + red[3];
}

// ---------------- HMMA GEMM: C = max(sqx_i + sqy_j - 2 * dot, 0) -----------
// 128x128 CTA tile, BK=32, 8 warps (2x4), warp tile 64x32, double-buffered.
#define BM 128
#define BN 128
#define BK 32
#define NITER (KK / BK)          // 48
#define SROW 40                  // smem row stride in bf16 elems (80 bytes)

__global__ __launch_bounds__(256, 2) void gemm_mma_kernel() {
    __shared__ __align__(16) __nv_bfloat16 As[2][BM * SROW];
    __shared__ __align__(16) __nv_bfloat16 Bs[2][BN * SROW];

    const int tid = threadIdx.x;
    const int wid = tid >> 5;
    const int lane = tid & 31;
    const int warp_m = wid >> 2;          // 0..1  (64 rows each)
    const int warp_n = wid & 3;           // 0..3  (32 cols each)
    const int brow = blockIdx.y * BM;
    const int bcol = blockIdx.x * BN;

    float acc[4][4][4];
    #pragma unroll
    for (int mi = 0; mi < 4; mi++)
        #pragma unroll
        for (int ni = 0; ni < 4; ni++)
            #pragma unroll
            for (int r = 0; r < 4; r++) acc[mi][ni][r] = 0.f;

    uint32_t sA[2] = { smem_u32(&As[0][0]), smem_u32(&As[1][0]) };
    uint32_t sB[2] = { smem_u32(&Bs[0][0]), smem_u32(&Bs[1][0]) };

    // global load mapping: idx -> row=idx/4, chunk=idx%4 (16B each); 512 idx per matrix
    const int r0l = tid >> 2, ch0 = (tid & 3);
    const int r1l = (tid + 256) >> 2, ch1 = (tid & 3);

    // prologue: tile 0 -> buf 0
    {
        const int k0 = 0;
        cp_async16(sA[0] + (uint32_t)(r0l * SROW + ch0 * 8) * 2, g_Xs + (size_t)(brow + r0l) * KK + k0 + ch0 * 8);
        cp_async16(sA[0] + (uint32_t)(r1l * SROW + ch1 * 8) * 2, g_Xs + (size_t)(brow + r1l) * KK + k0 + ch1 * 8);
        cp_async16(sB[0] + (uint32_t)(r0l * SROW + ch0 * 8) * 2, g_Ys + (size_t)(bcol + r0l) * KK + k0 + ch0 * 8);
        cp_async16(sB[0] + (uint32_t)(r1l * SROW + ch1 * 8) * 2, g_Ys + (size_t)(bcol + r1l) * KK + k0 + ch1 * 8);
        CP_COMMIT();
    }

    for (int c = 0; c < NITER; c++) {
        int buf = c & 1;
        if (c + 1 < NITER) {
            int nb = buf ^ 1;
            int k0 = (c + 1) * BK;
            cp_async16(sA[nb] + (uint32_t)(r0l * SROW + ch0 * 8) * 2, g_Xs + (size_t)(brow + r0l) * KK + k0 + ch0 * 8);
            cp_async16(sA[nb] + (uint32_t)(r1l * SROW + ch1 * 8) * 2, g_Xs + (size_t)(brow + r1l) * KK + k0 + ch1 * 8);
            cp_async16(sB[nb] + (uint32_t)(r0l * SROW + ch0 * 8) * 2, g_Ys + (size_t)(bcol + r0l) * KK + k0 + ch0 * 8);
            cp_async16(sB[nb] + (uint32_t)(r1l * SROW + ch1 * 8) * 2, g_Ys + (size_t)(bcol + r1l) * KK + k0 + ch1 * 8);
            CP_COMMIT();
            CP_WAIT(1);
        } else {
            CP_WAIT(0);
        }
        __syncthreads();

        #pragma unroll
        for (int ks = 0; ks < 2; ks++) {
            // A fragments: 4 m-tiles of 16
            uint32_t afr[4][4];
            #pragma unroll
            for (int mi = 0; mi < 4; mi++) {
                int row = warp_m * 64 + mi * 16 + (lane & 15);
                int col = ks * 16 + ((lane >> 4) << 3);
                ldmatrix_x4(afr[mi][0], afr[mi][1], afr[mi][2], afr[mi][3],
                            sA[buf] + (uint32_t)(row * SROW + col) * 2);
            }
            // B fragments: 4 n-tiles of 8 (two per ldmatrix.x4)
            uint32_t bfr[4][2];
            #pragma unroll
            for (int np = 0; np < 2; np++) {
                int nrow = warp_n * 32 + np * 16 + ((lane >> 4) << 3) + (lane & 7);
                int col  = ks * 16 + (((lane >> 3) & 1) << 3);
                uint32_t r0, r1, r2, r3;
                ldmatrix_x4(r0, r1, r2, r3, sB[buf] + (uint32_t)(nrow * SROW + col) * 2);
                bfr[np*2][0] = r0; bfr[np*2][1] = r1;
                bfr[np*2+1][0] = r2; bfr[np*2+1][1] = r3;
            }
            #pragma unroll
            for (int mi = 0; mi < 4; mi++)
                #pragma unroll
                for (int ni = 0; ni < 4; ni++)
                    mma_16816(acc[mi][ni], afr[mi], bfr[ni]);
        }
        __syncthreads();
    }

    // epilogue: C = max(sqx + sqy - 2*dot, 0)
    #pragma unroll
    for (int mi = 0; mi < 4; mi++) {
        int r0 = brow + warp_m * 64 + mi * 16 + (lane >> 2);
        float sx0 = g_sqx[r0];
        float sx1 = g_sqx[r0 + 8];
        #pragma unroll
        for (int ni = 0; ni < 4; ni++) {
            int cc = bcol + warp_n * 32 + ni * 8 + (lane & 3) * 2;
            float sy0 = g_sqy[cc], sy1 = g_sqy[cc + 1];
            float2 o0, o1;
            o0.x = fmaxf(sx0 + sy0 - 2.f * acc[mi][ni][0], 0.f);
            o0.y = fmaxf(sx0 + sy1 - 2.f * acc[mi][ni][1], 0.f);
            o1.x = fmaxf(sx1 + sy0 - 2.f * acc[mi][ni][2], 0.f);
            o1.y = fmaxf(sx1 + sy1 - 2.f * acc[mi][ni][3], 0.f);
            *(float2*)(g_C + (size_t)r0 * NN + cc)       = o0;
            *(float2*)(g_C + (size_t)(r0 + 8) * NN + cc) = o1;
        }
    }
}

// ---------------- fallback: sum of row dot products of normalized x,y ------
__global__ __launch_bounds__(128) void fallback_kernel() {
    int row = blockIdx.x;
    int tid = threadIdx.x;
    float4 x = ((const float4*)(g_X + (size_t)row * DD))[tid];
    float4 y = ((const float4*)(g_Y + (size_t)row * DD))[tid];
    float d = x.x*y.x + x.y*y.y + x.z*y.z + x.w*y.w;
    __shared__ float red[4];
    #pragma unroll
    for (int o = 16; o > 0; o >>= 1) d += __shfl_xor_sync(0xffffffffu, d, o);
    if ((tid & 31) == 0) red[tid >> 5] = d;
    __syncthreads();
    if (tid == 0) atomicAdd(&g_fb, red[0] + red[1] + red[2] + red[3]);
}

// ---------------- row pass: log_u_i = -LSE_j(-5*C_ij + log_v_j) ------------
__global__ __launch_bounds__(256) void row_lse_kernel() {
    int row = blockIdx.x;
    int tid = threadIdx.x;
    const float4* Cr = (const float4*)(g_C + (size_t)row * NN);
    const float4* Lv = (const float4*)g_logv;

    float m = NEGBIG, s = 0.f;
    for (int c = tid; c < NN / 4; c += 256) {
        float4 cv = Cr[c];
        float4 lv = Lv[c];
        float a;
        a = fmaf(-EPS_INV, cv.x, lv.x);
        if (a > m) { s = s * expf(m - a) + 1.f; m = a; } else s += expf(a - m);
        a = fmaf(-EPS_INV, cv.y, lv.y);
        if (a > m) { s = s * expf(m - a) + 1.f; m = a; } else s += expf(a - m);
        a = fmaf(-EPS_INV, cv.z, lv.z);
        if (a > m) { s = s * expf(m - a) + 1.f; m = a; } else s += expf(a - m);
        a = fmaf(-EPS_INV, cv.w, lv.w);
        if (a > m) { s = s * expf(m - a) + 1.f; m = a; } else s += expf(a - m);
    }

    __shared__ float sm[256], ss[256];
    sm[tid] = m; ss[tid] = s;
    __syncthreads();
    for (int o = 128; o > 0; o >>= 1) {
        if (tid < o) {
            float m1 = sm[tid], s1 = ss[tid];
            float m2 = sm[tid + o], s2 = ss[tid + o];
            float M = fmaxf(m1, m2);
            sm[tid] = M;
            ss[tid] = s1 * expf(m1 - M) + s2 * expf(m2 - M);
        }
        __syncthreads();
    }
    if (tid == 0) g_logu[row] = -(sm[0] + logf(ss[0]));
}

// ------------- column pass, phase 1: per (row-chunk, column) partial LSE ---
__global__ __launch_bounds__(256) void col_partial_kernel() {
    int col = blockIdx.y * 256 + threadIdx.x;
    int r0  = blockIdx.x * 256;
    __shared__ float slu[256];
    slu[threadIdx.x] = g_logu[r0 + threadIdx.x];
    __syncthreads();

    float m = NEGBIG, s = 0.f;
    const float* Cp = g_C + (size_t)r0 * NN + col;
    #pragma unroll 4
    for (int i = 0; i < 256; i++) {
        float a = fmaf(-EPS_INV, Cp[(size_t)i * NN], slu[i]);
        if (a > m) { s = s * expf(m - a) + 1.f; m = a; } else s += expf(a - m);
    }
    g_cm[blockIdx.x * NN + col] = m;
    g_cs[blockIdx.x * NN + col] = s;
}

// ------------- column pass, phase 2: combine 32 partials per column --------
__global__ __launch_bounds__(256) void col_combine_kernel() {
    int col = blockIdx.x * 256 + threadIdx.x;
    float M = NEGBIG;
    #pragma unroll
    for (int ch = 0; ch < 32; ch++) M = fmaxf(M, g_cm[ch * NN + col]);
    float S = 0.f;
    #pragma unroll
    for (int ch = 0; ch < 32; ch++) S += g_cs[ch * NN + col] * expf(g_cm[ch * NN + col] - M);
    g_logv[col] = -(M + logf(S));
}

// ------------- final: sum over all i,j of clip(exp(lu+lK+lv),0,1) * C ------
__global__ __launch_bounds__(256) void distance_kernel() {
    int row = blockIdx.x;
    int tid = threadIdx.x;
    float lu = g_logu[row];
    const float4* Cr = (const float4*)(g_C + (size_t)row * NN);
    const float4* Lv = (const float4*)g_logv;

    float sum = 0.f;
    for (int c = tid; c < NN / 4; c += 256) {
        float4 cv = Cr[c];
        float4 lv = Lv[c];
        float p;
        p = expf(fmaf(-EPS_INV, cv.x, lu + lv.x)); p = fminf(p, 1.f); sum = fmaf(p, cv.x, sum);
        p = expf(fmaf(-EPS_INV, cv.y, lu + lv.y)); p = fminf(p, 1.f); sum = fmaf(p, cv.y, sum);
        p = expf(fmaf(-EPS_INV, cv.z, lu + lv.z)); p = fminf(p, 1.f); sum = fmaf(p, cv.z, sum);
        p = expf(fmaf(-EPS_INV, cv.w, lu + lv.w)); p = fminf(p, 1.f); sum = fmaf(p, cv.w, sum);
    }

    __shared__ float red[8];
    #pragma unroll
    for (int o = 16; o > 0; o >>= 1) sum += __shfl_xor_sync(0xffffffffu, sum, o);
    if ((tid & 31) == 0) red[tid >> 5] = sum;
    __syncthreads();
    if (tid == 0) {
        float b = 0.f;
        #pragma unroll
        for (int w = 0; w < 8; w++) b += red[w];
        atomicAdd(&g_accum, b);
    }
}

// ---------------- finalize ----------------
__global__ void finalize_kernel(float* out) {
    float d  = g_accum / (float)NN;
    float fb = 1.f - g_fb / (float)NN;
    out[0] = (isnan(d) || isinf(d)) ? fb : d;
}

// ---------------- launch ----------------
extern "C" void kernel_launch(void* const* d_in, const int* in_sizes, int n_in,
                              void* d_out, int out_size) {
    const float* emb = (const float*)d_in[0];
    const float* tn  = (const float*)d_in[1];
    float* out = (float*)d_out;

    init_kernel<<<32, 256>>>();
    normalize_kernel<<<2 * NN, 128>>>(emb, tn);
    gemm_mma_kernel<<<dim3(NN / BN, NN / BM), 256>>>();
    fallback_kernel<<<NN, 128>>>();

    for (int it = 0; it < 10; it++) {
        row_lse_kernel<<<NN, 256>>>();
        col_partial_kernel<<<dim3(32, 32), 256>>>();
        col_combine_kernel<<<32, 256>>>();
    }

    distance_kernel<<<NN, 256>>>();
    finalize_kernel<<<1, 1>>>(out);
}

// round 4
// speedup vs baseline: 1.6614x; 1.1731x over previous
#include <cuda_runtime.h>
#include <cuda_bf16.h>
#include <cuda_fp16.h>
#include <math.h>
#include <stdint.h>

// Problem constants
#define NN 8192
#define DD 512
#define KK 1024                  // split-bf16: A=[hi|lo], B=[hi|hi] -> hi.hi + lo.hi
#define EPS_INV 5.0f             // epsilon = 0.1*2 = 0.2 ; log_K = -C/eps = -5*C
#define NEGBIG (-3.0e38f)

// ---------------- device scratch (static: allocation rules) ----------------
__device__ float g_X[NN * DD];              // normalized embeddings   16 MB
__device__ float g_Y[NN * DD];              // normalized target noise 16 MB
__device__ __nv_bfloat16 g_Xs[(size_t)NN * KK];  // A = [x_hi | x_lo]  16 MB
__device__ __nv_bfloat16 g_Ys[(size_t)NN * KK];  // B = [y_hi | y_hi]  16 MB
__device__ float g_sqx[NN];
__device__ float g_sqy[NN];
__device__ __half g_C[(size_t)NN * (size_t)NN];  // cost matrix, fp16, 128 MB
__device__ float g_logu[NN];
__device__ float g_logv[NN];
__device__ float g_cm[32 * NN];             // column partial maxes
__device__ float g_cs[32 * NN];             // column partial scaled sums
__device__ float g_accum;                   // sum(P*C)
__device__ float g_fb;                      // sum of row dots (fallback)

// ---------------- helpers ----------------
__device__ __forceinline__ uint32_t smem_u32(const void* p) {
    uint32_t a;
    asm("{ .reg .u64 t; cvta.to.shared.u64 t, %1; cvt.u32.u64 %0, t; }" : "=r"(a) : "l"(p));
    return a;
}
__device__ __forceinline__ void cp_async16(uint32_t s, const void* g) {
    asm volatile("cp.async.cg.shared.global [%0], [%1], 16;" :: "r"(s), "l"(g));
}
#define CP_COMMIT()  asm volatile("cp.async.commit_group;" ::: "memory")
#define CP_WAIT(n)   asm volatile("cp.async.wait_group %0;" :: "n"(n) : "memory")

__device__ __forceinline__ void ldmatrix_x4(uint32_t& r0, uint32_t& r1, uint32_t& r2, uint32_t& r3,
                                            uint32_t addr) {
    asm volatile("ldmatrix.sync.aligned.m8n8.x4.shared.b16 {%0,%1,%2,%3}, [%4];"
                 : "=r"(r0), "=r"(r1), "=r"(r2), "=r"(r3) : "r"(addr));
}
__device__ __forceinline__ void mma_16816(float* c, const uint32_t* a, const uint32_t* b) {
    asm volatile("mma.sync.aligned.m16n8k16.row.col.f32.bf16.bf16.f32 "
                 "{%0,%1,%2,%3}, {%4,%5,%6,%7}, {%8,%9}, {%0,%1,%2,%3};"
                 : "+f"(c[0]), "+f"(c[1]), "+f"(c[2]), "+f"(c[3])
                 : "r"(a[0]), "r"(a[1]), "r"(a[2]), "r"(a[3]), "r"(b[0]), "r"(b[1]));
}

// ---------------- init ----------------
__global__ void init_kernel() {
    int i = blockIdx.x * blockDim.x + threadIdx.x;
    if (i < NN) { g_logu[i] = 0.f; g_logv[i] = 0.f; }
    if (i == 0) { g_accum = 0.f; g_fb = 0.f; }
}

// ---------------- normalize + build bf16 split operands ----------------
__global__ __launch_bounds__(128) void normalize_kernel(const float* __restrict__ emb,
                                                        const float* __restrict__ tn) {
    int b = blockIdx.x;
    const float* src;
    float* dst;
    float* sqv;
    __nv_bfloat16* split;
    int is_x;
    int row;
    if (b < NN) { row = b;      src = emb + (size_t)row * DD; dst = g_X + (size_t)row * DD; sqv = g_sqx; split = g_Xs + (size_t)row * KK; is_x = 1; }
    else        { row = b - NN; src = tn  + (size_t)row * DD; dst = g_Y + (size_t)row * DD; sqv = g_sqy; split = g_Ys + (size_t)row * KK; is_x = 0; }

    int tid = threadIdx.x;
    float4 v = ((const float4*)src)[tid];
    float ss = v.x*v.x + v.y*v.y + v.z*v.z + v.w*v.w;

    __shared__ float red[4];
    #pragma unroll
    for (int o = 16; o > 0; o >>= 1) ss += __shfl_xor_sync(0xffffffffu, ss, o);
    if ((tid & 31) == 0) red[tid >> 5] = ss;
    __syncthreads();
    float tot = red[0] + red[1] + red[2] + red[3];

    float norm = sqrtf(tot);
    float inv  = 1.0f / fmaxf(norm, 1e-12f);
    float4 w;
    w.x = v.x * inv; w.y = v.y * inv; w.z = v.z * inv; w.w = v.w * inv;
    ((float4*)dst)[tid] = w;

    // bf16 hi/lo split
    __nv_bfloat16 hx = __float2bfloat16(w.x), hy = __float2bfloat16(w.y);
    __nv_bfloat16 hz = __float2bfloat16(w.z), hw = __float2bfloat16(w.w);
    __nv_bfloat16 lx = __float2bfloat16(w.x - __bfloat162float(hx));
    __nv_bfloat16 ly = __float2bfloat16(w.y - __bfloat162float(hy));
    __nv_bfloat16 lz = __float2bfloat16(w.z - __bfloat162float(hz));
    __nv_bfloat16 lw = __float2bfloat16(w.w - __bfloat162float(hw));

    uint32_t hi01 = (uint32_t)__bfloat16_as_ushort(hx) | ((uint32_t)__bfloat16_as_ushort(hy) << 16);
    uint32_t hi23 = (uint32_t)__bfloat16_as_ushort(hz) | ((uint32_t)__bfloat16_as_ushort(hw) << 16);
    uint32_t lo01 = (uint32_t)__bfloat16_as_ushort(lx) | ((uint32_t)__bfloat16_as_ushort(ly) << 16);
    uint32_t lo23 = (uint32_t)__bfloat16_as_ushort(lz) | ((uint32_t)__bfloat16_as_ushort(lw) << 16);

    int k = tid * 4;
    uint2 hi_pack = make_uint2(hi01, hi23);
    uint2 lo_pack = make_uint2(lo01, lo23);
    *(uint2*)(split + k) = hi_pack;            // segment 0: hi (both)
    if (is_x) {                                // A = [hi | lo]
        *(uint2*)(split + k + DD) = lo_pack;
    } else {                                   // B = [hi | hi]
        *(uint2*)(split + k + DD) = hi_pack;
    }

    float ss2 = w.x*w.x + w.y*w.y + w.z*w.z + w.w*w.w;
    #pragma unroll
    for (int o = 16; o > 0; o >>= 1) ss2 += __shfl_xor_sync(0xffffffffu, ss2, o);
    __syncthreads();
    if ((tid & 31) == 0) red[tid >> 5] = ss2;
    __syncthreads();
    if (tid == 0) sqv[row] = red[0] + red[1] + red[2] + red[3];
}

// ---------------- HMMA GEMM: C = max(sqx_i + sqy_j - 2 * dot, 0) -----------
// 128x128 CTA tile, BK=32, 8 warps (2x4), warp tile 64x32, double-buffered.
#define BM 128
#define BN 128
#define BK 32
#define NITER (KK / BK)          // 32
#define SROW 40                  // smem row stride in bf16 elems (80 bytes)

__global__ __launch_bounds__(256, 2) void gemm_mma_kernel() {
    __shared__ __align__(16) __nv_bfloat16 As[2][BM * SROW];
    __shared__ __align__(16) __nv_bfloat16 Bs[2][BN * SROW];

    const int tid = threadIdx.x;
    const int wid = tid >> 5;
    const int lane = tid & 31;
    const int warp_m = wid >> 2;          // 0..1  (64 rows each)
    const int warp_n = wid & 3;           // 0..3  (32 cols each)
    const int brow = blockIdx.y * BM;
    const int bcol = blockIdx.x * BN;

    float acc[4][4][4];
    #pragma unroll
    for (int mi = 0; mi < 4; mi++)
        #pragma unroll
        for (int ni = 0; ni < 4; ni++)
            #pragma unroll
            for (int r = 0; r < 4; r++) acc[mi][ni][r] = 0.f;

    uint32_t sA[2] = { smem_u32(&As[0][0]), smem_u32(&As[1][0]) };
    uint32_t sB[2] = { smem_u32(&Bs[0][0]), smem_u32(&Bs[1][0]) };

    const int r0l = tid >> 2, ch0 = (tid & 3);
    const int r1l = (tid + 256) >> 2, ch1 = (tid & 3);

    // prologue: tile 0 -> buf 0
    {
        const int k0 = 0;
        cp_async16(sA[0] + (uint32_t)(r0l * SROW + ch0 * 8) * 2, g_Xs + (size_t)(brow + r0l) * KK + k0 + ch0 * 8);
        cp_async16(sA[0] + (uint32_t)(r1l * SROW + ch1 * 8) * 2, g_Xs + (size_t)(brow + r1l) * KK + k0 + ch1 * 8);
        cp_async16(sB[0] + (uint32_t)(r0l * SROW + ch0 * 8) * 2, g_Ys + (size_t)(bcol + r0l) * KK + k0 + ch0 * 8);
        cp_async16(sB[0] + (uint32_t)(r1l * SROW + ch1 * 8) * 2, g_Ys + (size_t)(bcol + r1l) * KK + k0 + ch1 * 8);
        CP_COMMIT();
    }

    for (int c = 0; c < NITER; c++) {
        int buf = c & 1;
        if (c + 1 < NITER) {
            int nb = buf ^ 1;
            int k0 = (c + 1) * BK;
            cp_async16(sA[nb] + (uint32_t)(r0l * SROW + ch0 * 8) * 2, g_Xs + (size_t)(brow + r0l) * KK + k0 + ch0 * 8);
            cp_async16(sA[nb] + (uint32_t)(r1l * SROW + ch1 * 8) * 2, g_Xs + (size_t)(brow + r1l) * KK + k0 + ch1 * 8);
            cp_async16(sB[nb] + (uint32_t)(r0l * SROW + ch0 * 8) * 2, g_Ys + (size_t)(bcol + r0l) * KK + k0 + ch0 * 8);
            cp_async16(sB[nb] + (uint32_t)(r1l * SROW + ch1 * 8) * 2, g_Ys + (size_t)(bcol + r1l) * KK + k0 + ch1 * 8);
            CP_COMMIT();
            CP_WAIT(1);
        } else {
            CP_WAIT(0);
        }
        __syncthreads();

        #pragma unroll
        for (int ks = 0; ks < 2; ks++) {
            uint32_t afr[4][4];
            #pragma unroll
            for (int mi = 0; mi < 4; mi++) {
                int row = warp_m * 64 + mi * 16 + (lane & 15);
                int col = ks * 16 + ((lane >> 4) << 3);
                ldmatrix_x4(afr[mi][0], afr[mi][1], afr[mi][2], afr[mi][3],
                            sA[buf] + (uint32_t)(row * SROW + col) * 2);
            }
            uint32_t bfr[4][2];
            #pragma unroll
            for (int np = 0; np < 2; np++) {
                int nrow = warp_n * 32 + np * 16 + ((lane >> 4) << 3) + (lane & 7);
                int col  = ks * 16 + (((lane >> 3) & 1) << 3);
                uint32_t r0, r1, r2, r3;
                ldmatrix_x4(r0, r1, r2, r3, sB[buf] + (uint32_t)(nrow * SROW + col) * 2);
                bfr[np*2][0] = r0; bfr[np*2][1] = r1;
                bfr[np*2+1][0] = r2; bfr[np*2+1][1] = r3;
            }
            #pragma unroll
            for (int mi = 0; mi < 4; mi++)
                #pragma unroll
                for (int ni = 0; ni < 4; ni++)
                    mma_16816(acc[mi][ni], afr[mi], bfr[ni]);
        }
        __syncthreads();
    }

    // epilogue: C = max(sqx + sqy - 2*dot, 0), stored fp16
    #pragma unroll
    for (int mi = 0; mi < 4; mi++) {
        int r0 = brow + warp_m * 64 + mi * 16 + (lane >> 2);
        float sx0 = g_sqx[r0];
        float sx1 = g_sqx[r0 + 8];
        #pragma unroll
        for (int ni = 0; ni < 4; ni++) {
            int cc = bcol + warp_n * 32 + ni * 8 + (lane & 3) * 2;
            float sy0 = g_sqy[cc], sy1 = g_sqy[cc + 1];
            __half2 h0 = __floats2half2_rn(fmaxf(sx0 + sy0 - 2.f * acc[mi][ni][0], 0.f),
                                           fmaxf(sx0 + sy1 - 2.f * acc[mi][ni][1], 0.f));
            __half2 h1 = __floats2half2_rn(fmaxf(sx1 + sy0 - 2.f * acc[mi][ni][2], 0.f),
                                           fmaxf(sx1 + sy1 - 2.f * acc[mi][ni][3], 0.f));
            *(__half2*)(g_C + (size_t)r0 * NN + cc)       = h0;
            *(__half2*)(g_C + (size_t)(r0 + 8) * NN + cc) = h1;
        }
    }
}

// ---------------- fallback: sum of row dot products of normalized x,y ------
__global__ __launch_bounds__(128) void fallback_kernel() {
    int row = blockIdx.x;
    int tid = threadIdx.x;
    float4 x = ((const float4*)(g_X + (size_t)row * DD))[tid];
    float4 y = ((const float4*)(g_Y + (size_t)row * DD))[tid];
    float d = x.x*y.x + x.y*y.y + x.z*y.z + x.w*y.w;
    __shared__ float red[4];
    #pragma unroll
    for (int o = 16; o > 0; o >>= 1) d += __shfl_xor_sync(0xffffffffu, d, o);
    if ((tid & 31) == 0) red[tid >> 5] = d;
    __syncthreads();
    if (tid == 0) atomicAdd(&g_fb, red[0] + red[1] + red[2] + red[3]);
}

// online LSE accumulate helper
__device__ __forceinline__ void lse_acc(float a, float& m, float& s) {
    if (a > m) { s = s * __expf(m - a) + 1.f; m = a; } else s += __expf(a - m);
}

// ---------------- row pass: log_u_i = -LSE_j(-5*C_ij + log_v_j) ------------
__global__ __launch_bounds__(256) void row_lse_kernel() {
    int row = blockIdx.x;
    int tid = threadIdx.x;
    const uint4* Cr = (const uint4*)(g_C + (size_t)row * NN);   // 8 halves each
    const float4* Lv = (const float4*)g_logv;

    float m = NEGBIG, s = 0.f;
    for (int c = tid; c < NN / 8; c += 256) {
        uint4 cv = Cr[c];
        float4 lv0 = Lv[2*c], lv1 = Lv[2*c + 1];
        float2 c0 = __half22float2(*(const __half2*)&cv.x);
        float2 c1 = __half22float2(*(const __half2*)&cv.y);
        float2 c2 = __half22float2(*(const __half2*)&cv.z);
        float2 c3 = __half22float2(*(const __half2*)&cv.w);
        lse_acc(fmaf(-EPS_INV, c0.x, lv0.x), m, s);
        lse_acc(fmaf(-EPS_INV, c0.y, lv0.y), m, s);
        lse_acc(fmaf(-EPS_INV, c1.x, lv0.z), m, s);
        lse_acc(fmaf(-EPS_INV, c1.y, lv0.w), m, s);
        lse_acc(fmaf(-EPS_INV, c2.x, lv1.x), m, s);
        lse_acc(fmaf(-EPS_INV, c2.y, lv1.y), m, s);
        lse_acc(fmaf(-EPS_INV, c3.x, lv1.z), m, s);
        lse_acc(fmaf(-EPS_INV, c3.y, lv1.w), m, s);
    }

    __shared__ float sm[256], ss[256];
    sm[tid] = m; ss[tid] = s;
    __syncthreads();
    for (int o = 128; o > 0; o >>= 1) {
        if (tid < o) {
            float m1 = sm[tid], s1 = ss[tid];
            float m2 = sm[tid + o], s2 = ss[tid + o];
            float M = fmaxf(m1, m2);
            sm[tid] = M;
            ss[tid] = s1 * __expf(m1 - M) + s2 * __expf(m2 - M);
        }
        __syncthreads();
    }
    if (tid == 0) g_logu[row] = -(sm[0] + logf(ss[0]));
}

// ------------- column pass, phase 1: per (row-chunk, column) partial LSE ---
__global__ __launch_bounds__(256) void col_partial_kernel() {
    int col = blockIdx.y * 256 + threadIdx.x;
    int r0  = blockIdx.x * 256;
    __shared__ float slu[256];
    slu[threadIdx.x] = g_logu[r0 + threadIdx.x];
    __syncthreads();

    float m = NEGBIG, s = 0.f;
    const __half* Cp = g_C + (size_t)r0 * NN + col;
    #pragma unroll 4
    for (int i = 0; i < 256; i++) {
        float a = fmaf(-EPS_INV, __half2float(Cp[(size_t)i * NN]), slu[i]);
        lse_acc(a, m, s);
    }
    g_cm[blockIdx.x * NN + col] = m;
    g_cs[blockIdx.x * NN + col] = s;
}

// ------------- column pass, phase 2: combine 32 partials per column --------
__global__ __launch_bounds__(256) void col_combine_kernel() {
    int col = blockIdx.x * 256 + threadIdx.x;
    float M = NEGBIG;
    #pragma unroll
    for (int ch = 0; ch < 32; ch++) M = fmaxf(M, g_cm[ch * NN + col]);
    float S = 0.f;
    #pragma unroll
    for (int ch = 0; ch < 32; ch++) S += g_cs[ch * NN + col] * __expf(g_cm[ch * NN + col] - M);
    g_logv[col] = -(M + logf(S));
}

// ------------- final: sum over all i,j of clip(exp(lu+lK+lv),0,1) * C ------
__global__ __launch_bounds__(256) void distance_kernel() {
    int row = blockIdx.x;
    int tid = threadIdx.x;
    float lu = g_logu[row];
    const uint4* Cr = (const uint4*)(g_C + (size_t)row * NN);
    const float4* Lv = (const float4*)g_logv;

    float sum = 0.f;
    for (int c = tid; c < NN / 8; c += 256) {
        uint4 cv = Cr[c];
        float4 lv0 = Lv[2*c], lv1 = Lv[2*c + 1];
        float2 c0 = __half22float2(*(const __half2*)&cv.x);
        float2 c1 = __half22float2(*(const __half2*)&cv.y);
        float2 c2 = __half22float2(*(const __half2*)&cv.z);
        float2 c3 = __half22float2(*(const __half2*)&cv.w);
        float p;
        p = fminf(__expf(fmaf(-EPS_INV, c0.x, lu + lv0.x)), 1.f); sum = fmaf(p, c0.x, sum);
        p = fminf(__expf(fmaf(-EPS_INV, c0.y, lu + lv0.y)), 1.f); sum = fmaf(p, c0.y, sum);
        p = fminf(__expf(fmaf(-EPS_INV, c1.x, lu + lv0.z)), 1.f); sum = fmaf(p, c1.x, sum);
        p = fminf(__expf(fmaf(-EPS_INV, c1.y, lu + lv0.w)), 1.f); sum = fmaf(p, c1.y, sum);
        p = fminf(__expf(fmaf(-EPS_INV, c2.x, lu + lv1.x)), 1.f); sum = fmaf(p, c2.x, sum);
        p = fminf(__expf(fmaf(-EPS_INV, c2.y, lu + lv1.y)), 1.f); sum = fmaf(p, c2.y, sum);
        p = fminf(__expf(fmaf(-EPS_INV, c3.x, lu + lv1.z)), 1.f); sum = fmaf(p, c3.x, sum);
        p = fminf(__expf(fmaf(-EPS_INV, c3.y, lu + lv1.w)), 1.f); sum = fmaf(p, c3.y, sum);
    }

    __shared__ float red[8];
    #pragma unroll
    for (int o = 16; o > 0; o >>= 1) sum += __shfl_xor_sync(0xffffffffu, sum, o);
    if ((tid & 31) == 0) red[tid >> 5] = sum;
    __syncthreads();
    if (tid == 0) {
        float b = 0.f;
        #pragma unroll
        for (int w = 0; w < 8; w++) b += red[w];
        atomicAdd(&g_accum, b);
    }
}

// ---------------- finalize ----------------
__global__ void finalize_kernel(float* out) {
    float d  = g_accum / (float)NN;
    float fb = 1.f - g_fb / (float)NN;
    out[0] = (isnan(d) || isinf(d)) ? fb : d;
}

// ---------------- launch ----------------
extern "C" void kernel_launch(void* const* d_in, const int* in_sizes, int n_in,
                              void* d_out, int out_size) {
    const float* emb = (const float*)d_in[0];
    const float* tn  = (const float*)d_in[1];
    float* out = (float*)d_out;

    init_kernel<<<32, 256>>>();
    normalize_kernel<<<2 * NN, 128>>>(emb, tn);
    gemm_mma_kernel<<<dim3(NN / BN, NN / BM), 256>>>();
    fallback_kernel<<<NN, 128>>>();

    for (int it = 0; it < 10; it++) {
        row_lse_kernel<<<NN, 256>>>();
        col_partial_kernel<<<dim3(32, 32), 256>>>();
        col_combine_kernel<<<32, 256>>>();
    }

    distance_kernel<<<NN, 256>>>();
    finalize_kernel<<<1, 1>>>(out);
}

// round 5
// speedup vs baseline: 1.7704x; 1.0656x over previous
#include <cuda_runtime.h>
#include <cuda_bf16.h>
#include <cuda_fp16.h>
#include <math.h>
#include <stdint.h>

// Problem constants
#define NN 8192
#define DD 512
#define KK 1024                  // split-bf16: A=[hi|lo], B=[hi|hi] -> hi.hi + lo.hi
#define EPS_INV 5.0f             // epsilon = 0.1*2 = 0.2 ; log_K = -C/eps = -5*C
#define NEGBIG (-3.0e38f)

// ---------------- device scratch (static: allocation rules) ----------------
__device__ float g_X[NN * DD];              // normalized embeddings   16 MB
__device__ float g_Y[NN * DD];              // normalized target noise 16 MB
__device__ __nv_bfloat16 g_Xs[(size_t)NN * KK];  // A = [x_hi | x_lo]  16 MB
__device__ __nv_bfloat16 g_Ys[(size_t)NN * KK];  // B = [y_hi | y_hi]  16 MB
__device__ float g_sqx[NN];
__device__ float g_sqy[NN];
__device__ __half g_C[(size_t)NN * (size_t)NN];  // cost matrix, fp16, 128 MB
__device__ float g_logu[NN];
__device__ float g_logv[NN];
__device__ float g_cm[32 * NN];             // column partial maxes
__device__ float g_cs[32 * NN];             // column partial scaled sums
__device__ float g_accum;                   // sum(P*C)
__device__ float g_fb;                      // sum of row dots (fallback)

// ---------------- helpers ----------------
__device__ __forceinline__ uint32_t smem_u32(const void* p) {
    uint32_t a;
    asm("{ .reg .u64 t; cvta.to.shared.u64 t, %1; cvt.u32.u64 %0, t; }" : "=r"(a) : "l"(p));
    return a;
}
__device__ __forceinline__ void cp_async16(uint32_t s, const void* g) {
    asm volatile("cp.async.cg.shared.global [%0], [%1], 16;" :: "r"(s), "l"(g));
}
#define CP_COMMIT()  asm volatile("cp.async.commit_group;" ::: "memory")
#define CP_WAIT(n)   asm volatile("cp.async.wait_group %0;" :: "n"(n) : "memory")

__device__ __forceinline__ void ldmatrix_x4(uint32_t& r0, uint32_t& r1, uint32_t& r2, uint32_t& r3,
                                            uint32_t addr) {
    asm volatile("ldmatrix.sync.aligned.m8n8.x4.shared.b16 {%0,%1,%2,%3}, [%4];"
                 : "=r"(r0), "=r"(r1), "=r"(r2), "=r"(r3) : "r"(addr));
}
__device__ __forceinline__ void mma_16816(float* c, const uint32_t* a, const uint32_t* b) {
    asm volatile("mma.sync.aligned.m16n8k16.row.col.f32.bf16.bf16.f32 "
                 "{%0,%1,%2,%3}, {%4,%5,%6,%7}, {%8,%9}, {%0,%1,%2,%3};"
                 : "+f"(c[0]), "+f"(c[1]), "+f"(c[2]), "+f"(c[3])
                 : "r"(a[0]), "r"(a[1]), "r"(a[2]), "r"(a[3]), "r"(b[0]), "r"(b[1]));
}

// ---------------- init ----------------
__global__ void init_kernel() {
    int i = blockIdx.x * blockDim.x + threadIdx.x;
    if (i < NN) { g_logu[i] = 0.f; g_logv[i] = 0.f; }
    if (i == 0) { g_accum = 0.f; g_fb = 0.f; }
}

// ---------------- normalize + build bf16 split operands ----------------
__global__ __launch_bounds__(128) void normalize_kernel(const float* __restrict__ emb,
                                                        const float* __restrict__ tn) {
    int b = blockIdx.x;
    const float* src;
    float* dst;
    float* sqv;
    __nv_bfloat16* split;
    int is_x;
    int row;
    if (b < NN) { row = b;      src = emb + (size_t)row * DD; dst = g_X + (size_t)row * DD; sqv = g_sqx; split = g_Xs + (size_t)row * KK; is_x = 1; }
    else        { row = b - NN; src = tn  + (size_t)row * DD; dst = g_Y + (size_t)row * DD; sqv = g_sqy; split = g_Ys + (size_t)row * KK; is_x = 0; }

    int tid = threadIdx.x;
    float4 v = ((const float4*)src)[tid];
    float ss = v.x*v.x + v.y*v.y + v.z*v.z + v.w*v.w;

    __shared__ float red[4];
    #pragma unroll
    for (int o = 16; o > 0; o >>= 1) ss += __shfl_xor_sync(0xffffffffu, ss, o);
    if ((tid & 31) == 0) red[tid >> 5] = ss;
    __syncthreads();
    float tot = red[0] + red[1] + red[2] + red[3];

    float norm = sqrtf(tot);
    float inv  = 1.0f / fmaxf(norm, 1e-12f);
    float4 w;
    w.x = v.x * inv; w.y = v.y * inv; w.z = v.z * inv; w.w = v.w * inv;
    ((float4*)dst)[tid] = w;

    // bf16 hi/lo split
    __nv_bfloat16 hx = __float2bfloat16(w.x), hy = __float2bfloat16(w.y);
    __nv_bfloat16 hz = __float2bfloat16(w.z), hw = __float2bfloat16(w.w);
    __nv_bfloat16 lx = __float2bfloat16(w.x - __bfloat162float(hx));
    __nv_bfloat16 ly = __float2bfloat16(w.y - __bfloat162float(hy));
    __nv_bfloat16 lz = __float2bfloat16(w.z - __bfloat162float(hz));
    __nv_bfloat16 lw = __float2bfloat16(w.w - __bfloat162float(hw));

    uint32_t hi01 = (uint32_t)__bfloat16_as_ushort(hx) | ((uint32_t)__bfloat16_as_ushort(hy) << 16);
    uint32_t hi23 = (uint32_t)__bfloat16_as_ushort(hz) | ((uint32_t)__bfloat16_as_ushort(hw) << 16);
    uint32_t lo01 = (uint32_t)__bfloat16_as_ushort(lx) | ((uint32_t)__bfloat16_as_ushort(ly) << 16);
    uint32_t lo23 = (uint32_t)__bfloat16_as_ushort(lz) | ((uint32_t)__bfloat16_as_ushort(lw) << 16);

    int k = tid * 4;
    uint2 hi_pack = make_uint2(hi01, hi23);
    uint2 lo_pack = make_uint2(lo01, lo23);
    *(uint2*)(split + k) = hi_pack;            // segment 0: hi (both)
    if (is_x) {                                // A = [hi | lo]
        *(uint2*)(split + k + DD) = lo_pack;
    } else {                                   // B = [hi | hi]
        *(uint2*)(split + k + DD) = hi_pack;
    }

    float ss2 = w.x*w.x + w.y*w.y + w.z*w.z + w.w*w.w;
    #pragma unroll
    for (int o = 16; o > 0; o >>= 1) ss2 += __shfl_xor_sync(0xffffffffu, ss2, o);
    __syncthreads();
    if ((tid & 31) == 0) red[tid >> 5] = ss2;
    __syncthreads();
    if (tid == 0) sqv[row] = red[0] + red[1] + red[2] + red[3];
}

// ---------------- HMMA GEMM: C = max(sqx_i + sqy_j - 2 * dot, 0) -----------
// 128x128 CTA tile, 4 warps (2x2), warp tile 64x64, BK=32, 3-stage cp.async.
#define BM 128
#define BN 128
#define BK 32
#define NITER (KK / BK)          // 32
#define SROW 40                  // smem row stride in bf16 elems (80 bytes)
#define STAGES 3
#define A_BYTES (BM * SROW * 2)          // 10240
#define STAGE_BYTES (2 * A_BYTES)        // 20480 (A + B)
#define GEMM_SMEM (STAGES * STAGE_BYTES) // 61440

__global__ __launch_bounds__(128, 2) void gemm_mma_kernel() {
    extern __shared__ __align__(16) char smem[];
    const int tid = threadIdx.x;
    const int wid = tid >> 5;
    const int lane = tid & 31;
    const int warp_m = wid >> 1;          // 0..1  (64 rows each)
    const int warp_n = wid & 1;           // 0..1  (64 cols each)
    const int brow = blockIdx.y * BM;
    const int bcol = blockIdx.x * BN;

    float acc[4][8][4];
    #pragma unroll
    for (int mi = 0; mi < 4; mi++)
        #pragma unroll
        for (int ni = 0; ni < 8; ni++)
            #pragma unroll
            for (int r = 0; r < 4; r++) acc[mi][ni][r] = 0.f;

    uint32_t sbase = smem_u32(smem);

    // global load mapping: 512 x 16B chunks per matrix, 128 threads -> 4 each
    // idx = i*128 + tid; row = idx>>2 (0..127), ch = idx&3
    // prologue: stages 0, 1
    #pragma unroll
    for (int s = 0; s < STAGES - 1; s++) {
        int k0 = s * BK;
        uint32_t sa = sbase + s * STAGE_BYTES;
        uint32_t sb = sa + A_BYTES;
        #pragma unroll
        for (int i = 0; i < 4; i++) {
            int idx = i * 128 + tid;
            int r = idx >> 2, ch = idx & 3;
            cp_async16(sa + (uint32_t)(r * SROW + ch * 8) * 2, g_Xs + (size_t)(brow + r) * KK + k0 + ch * 8);
        }
        #pragma unroll
        for (int i = 0; i < 4; i++) {
            int idx = i * 128 + tid;
            int r = idx >> 2, ch = idx & 3;
            cp_async16(sb + (uint32_t)(r * SROW + ch * 8) * 2, g_Ys + (size_t)(bcol + r) * KK + k0 + ch * 8);
        }
        CP_COMMIT();
    }

    int buf = 0;
    for (int c = 0; c < NITER; c++) {
        CP_WAIT(STAGES - 2);
        __syncthreads();

        // prefetch stage c+2 into the buffer freed by compute of c-1
        if (c + STAGES - 1 < NITER) {
            int ps = (c + STAGES - 1) % STAGES;
            int k0 = (c + STAGES - 1) * BK;
            uint32_t sa = sbase + ps * STAGE_BYTES;
            uint32_t sb = sa + A_BYTES;
            #pragma unroll
            for (int i = 0; i < 4; i++) {
                int idx = i * 128 + tid;
                int r = idx >> 2, ch = idx & 3;
                cp_async16(sa + (uint32_t)(r * SROW + ch * 8) * 2, g_Xs + (size_t)(brow + r) * KK + k0 + ch * 8);
            }
            #pragma unroll
            for (int i = 0; i < 4; i++) {
                int idx = i * 128 + tid;
                int r = idx >> 2, ch = idx & 3;
                cp_async16(sb + (uint32_t)(r * SROW + ch * 8) * 2, g_Ys + (size_t)(bcol + r) * KK + k0 + ch * 8);
            }
        }
        CP_COMMIT();

        uint32_t sa = sbase + buf * STAGE_BYTES;
        uint32_t sb = sa + A_BYTES;

        #pragma unroll
        for (int ks = 0; ks < 2; ks++) {
            uint32_t afr[4][4];
            #pragma unroll
            for (int mi = 0; mi < 4; mi++) {
                int row = warp_m * 64 + mi * 16 + (lane & 15);
                int col = ks * 16 + ((lane >> 4) << 3);
                ldmatrix_x4(afr[mi][0], afr[mi][1], afr[mi][2], afr[mi][3],
                            sa + (uint32_t)(row * SROW + col) * 2);
            }
            uint32_t bfr[8][2];
            #pragma unroll
            for (int np = 0; np < 4; np++) {
                int nrow = warp_n * 64 + np * 16 + ((lane >> 4) << 3) + (lane & 7);
                int col  = ks * 16 + (((lane >> 3) & 1) << 3);
                uint32_t r0, r1, r2, r3;
                ldmatrix_x4(r0, r1, r2, r3, sb + (uint32_t)(nrow * SROW + col) * 2);
                bfr[np*2][0] = r0; bfr[np*2][1] = r1;
                bfr[np*2+1][0] = r2; bfr[np*2+1][1] = r3;
            }
            #pragma unroll
            for (int mi = 0; mi < 4; mi++)
                #pragma unroll
                for (int ni = 0; ni < 8; ni++)
                    mma_16816(acc[mi][ni], afr[mi], bfr[ni]);
        }
        buf = (buf + 1 == STAGES) ? 0 : buf + 1;
    }

    // epilogue: C = max(sqx + sqy - 2*dot, 0), stored fp16
    #pragma unroll
    for (int mi = 0; mi < 4; mi++) {
        int r0 = brow + warp_m * 64 + mi * 16 + (lane >> 2);
        float sx0 = g_sqx[r0];
        float sx1 = g_sqx[r0 + 8];
        #pragma unroll
        for (int ni = 0; ni < 8; ni++) {
            int cc = bcol + warp_n * 64 + ni * 8 + (lane & 3) * 2;
            float sy0 = g_sqy[cc], sy1 = g_sqy[cc + 1];
            __half2 h0 = __floats2half2_rn(fmaxf(sx0 + sy0 - 2.f * acc[mi][ni][0], 0.f),
                                           fmaxf(sx0 + sy1 - 2.f * acc[mi][ni][1], 0.f));
            __half2 h1 = __floats2half2_rn(fmaxf(sx1 + sy0 - 2.f * acc[mi][ni][2], 0.f),
                                           fmaxf(sx1 + sy1 - 2.f * acc[mi][ni][3], 0.f));
            *(__half2*)(g_C + (size_t)r0 * NN + cc)       = h0;
            *(__half2*)(g_C + (size_t)(r0 + 8) * NN + cc) = h1;
        }
    }
}

// ---------------- fallback: sum of row dot products of normalized x,y ------
__global__ __launch_bounds__(128) void fallback_kernel() {
    int row = blockIdx.x;
    int tid = threadIdx.x;
    float4 x = ((const float4*)(g_X + (size_t)row * DD))[tid];
    float4 y = ((const float4*)(g_Y + (size_t)row * DD))[tid];
    float d = x.x*y.x + x.y*y.y + x.z*y.z + x.w*y.w;
    __shared__ float red[4];
    #pragma unroll
    for (int o = 16; o > 0; o >>= 1) d += __shfl_xor_sync(0xffffffffu, d, o);
    if ((tid & 31) == 0) red[tid >> 5] = d;
    __syncthreads();
    if (tid == 0) atomicAdd(&g_fb, red[0] + red[1] + red[2] + red[3]);
}

// online LSE accumulate helper
__device__ __forceinline__ void lse_acc(float a, float& m, float& s) {
    if (a > m) { s = s * __expf(m - a) + 1.f; m = a; } else s += __expf(a - m);
}

// ---------------- row pass: log_u_i = -LSE_j(-5*C_ij + log_v_j) ------------
__global__ __launch_bounds__(256) void row_lse_kernel() {
    int row = blockIdx.x;
    int tid = threadIdx.x;
    const uint4* Cr = (const uint4*)(g_C + (size_t)row * NN);   // 8 halves each
    const float4* Lv = (const float4*)g_logv;

    float m = NEGBIG, s = 0.f;
    for (int c = tid; c < NN / 8; c += 256) {
        uint4 cv = Cr[c];
        float4 lv0 = Lv[2*c], lv1 = Lv[2*c + 1];
        float2 c0 = __half22float2(*(const __half2*)&cv.x);
        float2 c1 = __half22float2(*(const __half2*)&cv.y);
        float2 c2 = __half22float2(*(const __half2*)&cv.z);
        float2 c3 = __half22float2(*(const __half2*)&cv.w);
        lse_acc(fmaf(-EPS_INV, c0.x, lv0.x), m, s);
        lse_acc(fmaf(-EPS_INV, c0.y, lv0.y), m, s);
        lse_acc(fmaf(-EPS_INV, c1.x, lv0.z), m, s);
        lse_acc(fmaf(-EPS_INV, c1.y, lv0.w), m, s);
        lse_acc(fmaf(-EPS_INV, c2.x, lv1.x), m, s);
        lse_acc(fmaf(-EPS_INV, c2.y, lv1.y), m, s);
        lse_acc(fmaf(-EPS_INV, c3.x, lv1.z), m, s);
        lse_acc(fmaf(-EPS_INV, c3.y, lv1.w), m, s);
    }

    __shared__ float sm[256], ss[256];
    sm[tid] = m; ss[tid] = s;
    __syncthreads();
    for (int o = 128; o > 0; o >>= 1) {
        if (tid < o) {
            float m1 = sm[tid], s1 = ss[tid];
            float m2 = sm[tid + o], s2 = ss[tid + o];
            float M = fmaxf(m1, m2);
            sm[tid] = M;
            ss[tid] = s1 * __expf(m1 - M) + s2 * __expf(m2 - M);
        }
        __syncthreads();
    }
    if (tid == 0) g_logu[row] = -(sm[0] + logf(ss[0]));
}

// ------------- column pass, phase 1: per (row-chunk, column) partial LSE ---
__global__ __launch_bounds__(256) void col_partial_kernel() {
    int col = blockIdx.y * 256 + threadIdx.x;
    int r0  = blockIdx.x * 256;
    __shared__ float slu[256];
    slu[threadIdx.x] = g_logu[r0 + threadIdx.x];
    __syncthreads();

    float m = NEGBIG, s = 0.f;
    const __half* Cp = g_C + (size_t)r0 * NN + col;
    #pragma unroll 4
    for (int i = 0; i < 256; i++) {
        float a = fmaf(-EPS_INV, __half2float(Cp[(size_t)i * NN]), slu[i]);
        lse_acc(a, m, s);
    }
    g_cm[blockIdx.x * NN + col] = m;
    g_cs[blockIdx.x * NN + col] = s;
}

// ------------- column pass, phase 2: combine 32 partials per column --------
__global__ __launch_bounds__(256) void col_combine_kernel() {
    int col = blockIdx.x * 256 + threadIdx.x;
    float M = NEGBIG;
    #pragma unroll
    for (int ch = 0; ch < 32; ch++) M = fmaxf(M, g_cm[ch * NN + col]);
    float S = 0.f;
    #pragma unroll
    for (int ch = 0; ch < 32; ch++) S += g_cs[ch * NN + col] * __expf(g_cm[ch * NN + col] - M);
    g_logv[col] = -(M + logf(S));
}

// ------------- final: sum over all i,j of clip(exp(lu+lK+lv),0,1) * C ------
__global__ __launch_bounds__(256) void distance_kernel() {
    int row = blockIdx.x;
    int tid = threadIdx.x;
    float lu = g_logu[row];
    const uint4* Cr = (const uint4*)(g_C + (size_t)row * NN);
    const float4* Lv = (const float4*)g_logv;

    float sum = 0.f;
    for (int c = tid; c < NN / 8; c += 256) {
        uint4 cv = Cr[c];
        float4 lv0 = Lv[2*c], lv1 = Lv[2*c + 1];
        float2 c0 = __half22float2(*(const __half2*)&cv.x);
        float2 c1 = __half22float2(*(const __half2*)&cv.y);
        float2 c2 = __half22float2(*(const __half2*)&cv.z);
        float2 c3 = __half22float2(*(const __half2*)&cv.w);
        float p;
        p = fminf(__expf(fmaf(-EPS_INV, c0.x, lu + lv0.x)), 1.f); sum = fmaf(p, c0.x, sum);
        p = fminf(__expf(fmaf(-EPS_INV, c0.y, lu + lv0.y)), 1.f); sum = fmaf(p, c0.y, sum);
        p = fminf(__expf(fmaf(-EPS_INV, c1.x, lu + lv0.z)), 1.f); sum = fmaf(p, c1.x, sum);
        p = fminf(__expf(fmaf(-EPS_INV, c1.y, lu + lv0.w)), 1.f); sum = fmaf(p, c1.y, sum);
        p = fminf(__expf(fmaf(-EPS_INV, c2.x, lu + lv1.x)), 1.f); sum = fmaf(p, c2.x, sum);
        p = fminf(__expf(fmaf(-EPS_INV, c2.y, lu + lv1.y)), 1.f); sum = fmaf(p, c2.y, sum);
        p = fminf(__expf(fmaf(-EPS_INV, c3.x, lu + lv1.z)), 1.f); sum = fmaf(p, c3.x, sum);
        p = fminf(__expf(fmaf(-EPS_INV, c3.y, lu + lv1.w)), 1.f); sum = fmaf(p, c3.y, sum);
    }

    __shared__ float red[8];
    #pragma unroll
    for (int o = 16; o > 0; o >>= 1) sum += __shfl_xor_sync(0xffffffffu, sum, o);
    if ((tid & 31) == 0) red[tid >> 5] = sum;
    __syncthreads();
    if (tid == 0) {
        float b = 0.f;
        #pragma unroll
        for (int w = 0; w < 8; w++) b += red[w];
        atomicAdd(&g_accum, b);
    }
}

// ---------------- finalize ----------------
__global__ void finalize_kernel(float* out) {
    float d  = g_accum / (float)NN;
    float fb = 1.f - g_fb / (float)NN;
    out[0] = (isnan(d) || isinf(d)) ? fb : d;
}

// ---------------- launch ----------------
extern "C" void kernel_launch(void* const* d_in, const int* in_sizes, int n_in,
                              void* d_out, int out_size) {
    const float* emb = (const float*)d_in[0];
    const float* tn  = (const float*)d_in[1];
    float* out = (float*)d_out;

    cudaFuncSetAttribute(gemm_mma_kernel, cudaFuncAttributeMaxDynamicSharedMemorySize, GEMM_SMEM);

    init_kernel<<<32, 256>>>();
    normalize_kernel<<<2 * NN, 128>>>(emb, tn);
    gemm_mma_kernel<<<dim3(NN / BN, NN / BM), 128, GEMM_SMEM>>>();
    fallback_kernel<<<NN, 128>>>();

    for (int it = 0; it < 10; it++) {
        row_lse_kernel<<<NN, 256>>>();
        col_partial_kernel<<<dim3(32, 32), 256>>>();
        col_combine_kernel<<<32, 256>>>();
    }

    distance_kernel<<<NN, 256>>>();
    finalize_kernel<<<1, 1>>>(out);
}

// round 6
// speedup vs baseline: 1.9216x; 1.0854x over previous
#include <cuda_runtime.h>
#include <cuda_fp16.h>
#include <math.h>
#include <stdint.h>

// Problem constants
#define NN 8192
#define DD 512
#define EPS_INV 5.0f             // epsilon = 0.1*2 = 0.2 ; log_K = -C/eps = -5*C
#define NEGBIG (-3.0e38f)

// ---------------- device scratch (static: allocation rules) ----------------
__device__ __half g_Xh[NN * DD];            // normalized embeddings, fp16   8 MB
__device__ __half g_Yh[NN * DD];            // normalized target noise, fp16 8 MB
__device__ float g_sqx[NN];
__device__ float g_sqy[NN];
__device__ __half g_C[(size_t)NN * (size_t)NN];  // cost matrix, fp16, 128 MB
__device__ float g_logu[NN];
__device__ float g_logv[NN];
__device__ float g_cm[32 * NN];             // column partial maxes
__device__ float g_cs[32 * NN];             // column partial scaled sums
__device__ float g_accum;                   // sum(P*C)
__device__ float g_fb;                      // sum of row dots (fallback)

// ---------------- helpers ----------------
__device__ __forceinline__ uint32_t smem_u32(const void* p) {
    uint32_t a;
    asm("{ .reg .u64 t; cvta.to.shared.u64 t, %1; cvt.u32.u64 %0, t; }" : "=r"(a) : "l"(p));
    return a;
}
__device__ __forceinline__ void cp_async16(uint32_t s, const void* g) {
    asm volatile("cp.async.cg.shared.global [%0], [%1], 16;" :: "r"(s), "l"(g));
}
#define CP_COMMIT()  asm volatile("cp.async.commit_group;" ::: "memory")
#define CP_WAIT(n)   asm volatile("cp.async.wait_group %0;" :: "n"(n) : "memory")

__device__ __forceinline__ void ldmatrix_x4(uint32_t& r0, uint32_t& r1, uint32_t& r2, uint32_t& r3,
                                            uint32_t addr) {
    asm volatile("ldmatrix.sync.aligned.m8n8.x4.shared.b16 {%0,%1,%2,%3}, [%4];"
                 : "=r"(r0), "=r"(r1), "=r"(r2), "=r"(r3) : "r"(addr));
}
__device__ __forceinline__ void mma_16816(float* c, const uint32_t* a, const uint32_t* b) {
    asm volatile("mma.sync.aligned.m16n8k16.row.col.f32.f16.f16.f32 "
                 "{%0,%1,%2,%3}, {%4,%5,%6,%7}, {%8,%9}, {%0,%1,%2,%3};"
                 : "+f"(c[0]), "+f"(c[1]), "+f"(c[2]), "+f"(c[3])
                 : "r"(a[0]), "r"(a[1]), "r"(a[2]), "r"(a[3]), "r"(b[0]), "r"(b[1]));
}

// ---------------- init ----------------
__global__ void init_kernel() {
    int i = blockIdx.x * blockDim.x + threadIdx.x;
    if (i < NN) { g_logu[i] = 0.f; g_logv[i] = 0.f; }
    if (i == 0) { g_accum = 0.f; g_fb = 0.f; }
}

// ---------------- normalize: fp32 in -> fp16 normalized + sq --------------
__global__ __launch_bounds__(128) void normalize_kernel(const float* __restrict__ emb,
                                                        const float* __restrict__ tn) {
    int b = blockIdx.x;
    const float* src;
    __half* dst;
    float* sqv;
    int row;
    if (b < NN) { row = b;      src = emb + (size_t)row * DD; dst = g_Xh + (size_t)row * DD; sqv = g_sqx; }
    else        { row = b - NN; src = tn  + (size_t)row * DD; dst = g_Yh + (size_t)row * DD; sqv = g_sqy; }

    int tid = threadIdx.x;
    float4 v = ((const float4*)src)[tid];
    float ss = v.x*v.x + v.y*v.y + v.z*v.z + v.w*v.w;

    __shared__ float red[4];
    #pragma unroll
    for (int o = 16; o > 0; o >>= 1) ss += __shfl_xor_sync(0xffffffffu, ss, o);
    if ((tid & 31) == 0) red[tid >> 5] = ss;
    __syncthreads();
    float tot = red[0] + red[1] + red[2] + red[3];

    float norm = sqrtf(tot);
    float inv  = 1.0f / fmaxf(norm, 1e-12f);
    float4 w;
    w.x = v.x * inv; w.y = v.y * inv; w.z = v.z * inv; w.w = v.w * inv;

    // fp16 store (4 halves = 8B)
    __half2 h01 = __floats2half2_rn(w.x, w.y);
    __half2 h23 = __floats2half2_rn(w.z, w.w);
    *(uint2*)(dst + tid * 4) = make_uint2(*(uint32_t*)&h01, *(uint32_t*)&h23);

    // sq of the fp32 normalized values (matches reference)
    float ss2 = w.x*w.x + w.y*w.y + w.z*w.z + w.w*w.w;
    #pragma unroll
    for (int o = 16; o > 0; o >>= 1) ss2 += __shfl_xor_sync(0xffffffffu, ss2, o);
    __syncthreads();
    if ((tid & 31) == 0) red[tid >> 5] = ss2;
    __syncthreads();
    if (tid == 0) sqv[row] = red[0] + red[1] + red[2] + red[3];
}

// ---------------- HMMA GEMM: C = max(sqx_i + sqy_j - 2 * dot, 0) -----------
// 128x128 CTA tile, 4 warps (2x2), warp tile 64x64, BK=32, 3-stage cp.async.
// Single fp16 operand, K = 512.
#define BM 128
#define BN 128
#define BK 32
#define NITER (DD / BK)          // 16
#define SROW 40                  // smem row stride in halves (80 bytes)
#define STAGES 3
#define A_BYTES (BM * SROW * 2)          // 10240
#define STAGE_BYTES (2 * A_BYTES)        // 20480 (A + B)
#define GEMM_SMEM (STAGES * STAGE_BYTES) // 61440

__global__ __launch_bounds__(128, 2) void gemm_mma_kernel() {
    extern __shared__ __align__(16) char smem[];
    const int tid = threadIdx.x;
    const int wid = tid >> 5;
    const int lane = tid & 31;
    const int warp_m = wid >> 1;          // 0..1  (64 rows each)
    const int warp_n = wid & 1;           // 0..1  (64 cols each)
    const int brow = blockIdx.y * BM;
    const int bcol = blockIdx.x * BN;

    float acc[4][8][4];
    #pragma unroll
    for (int mi = 0; mi < 4; mi++)
        #pragma unroll
        for (int ni = 0; ni < 8; ni++)
            #pragma unroll
            for (int r = 0; r < 4; r++) acc[mi][ni][r] = 0.f;

    uint32_t sbase = smem_u32(smem);

    // global load mapping: 512 x 16B chunks per matrix, 128 threads -> 4 each
    #pragma unroll
    for (int s = 0; s < STAGES - 1; s++) {
        int k0 = s * BK;
        uint32_t sa = sbase + s * STAGE_BYTES;
        uint32_t sb = sa + A_BYTES;
        #pragma unroll
        for (int i = 0; i < 4; i++) {
            int idx = i * 128 + tid;
            int r = idx >> 2, ch = idx & 3;
            cp_async16(sa + (uint32_t)(r * SROW + ch * 8) * 2, g_Xh + (size_t)(brow + r) * DD + k0 + ch * 8);
        }
        #pragma unroll
        for (int i = 0; i < 4; i++) {
            int idx = i * 128 + tid;
            int r = idx >> 2, ch = idx & 3;
            cp_async16(sb + (uint32_t)(r * SROW + ch * 8) * 2, g_Yh + (size_t)(bcol + r) * DD + k0 + ch * 8);
        }
        CP_COMMIT();
    }

    int buf = 0;
    for (int c = 0; c < NITER; c++) {
        CP_WAIT(STAGES - 2);
        __syncthreads();

        if (c + STAGES - 1 < NITER) {
            int ps = (c + STAGES - 1) % STAGES;
            int k0 = (c + STAGES - 1) * BK;
            uint32_t sa = sbase + ps * STAGE_BYTES;
            uint32_t sb = sa + A_BYTES;
            #pragma unroll
            for (int i = 0; i < 4; i++) {
                int idx = i * 128 + tid;
                int r = idx >> 2, ch = idx & 3;
                cp_async16(sa + (uint32_t)(r * SROW + ch * 8) * 2, g_Xh + (size_t)(brow + r) * DD + k0 + ch * 8);
            }
            #pragma unroll
            for (int i = 0; i < 4; i++) {
                int idx = i * 128 + tid;
                int r = idx >> 2, ch = idx & 3;
                cp_async16(sb + (uint32_t)(r * SROW + ch * 8) * 2, g_Yh + (size_t)(bcol + r) * DD + k0 + ch * 8);
            }
        }
        CP_COMMIT();

        uint32_t sa = sbase + buf * STAGE_BYTES;
        uint32_t sb = sa + A_BYTES;

        #pragma unroll
        for (int ks = 0; ks < 2; ks++) {
            uint32_t afr[4][4];
            #pragma unroll
            for (int mi = 0; mi < 4; mi++) {
                int row = warp_m * 64 + mi * 16 + (lane & 15);
                int col = ks * 16 + ((lane >> 4) << 3);
                ldmatrix_x4(afr[mi][0], afr[mi][1], afr[mi][2], afr[mi][3],
                            sa + (uint32_t)(row * SROW + col) * 2);
            }
            uint32_t bfr[8][2];
            #pragma unroll
            for (int np = 0; np < 4; np++) {
                int nrow = warp_n * 64 + np * 16 + ((lane >> 4) << 3) + (lane & 7);
                int col  = ks * 16 + (((lane >> 3) & 1) << 3);
                uint32_t r0, r1, r2, r3;
                ldmatrix_x4(r0, r1, r2, r3, sb + (uint32_t)(nrow * SROW + col) * 2);
                bfr[np*2][0] = r0; bfr[np*2][1] = r1;
                bfr[np*2+1][0] = r2; bfr[np*2+1][1] = r3;
            }
            #pragma unroll
            for (int mi = 0; mi < 4; mi++)
                #pragma unroll
                for (int ni = 0; ni < 8; ni++)
                    mma_16816(acc[mi][ni], afr[mi], bfr[ni]);
        }
        buf = (buf + 1 == STAGES) ? 0 : buf + 1;
    }

    // epilogue: C = max(sqx + sqy - 2*dot, 0), stored fp16
    #pragma unroll
    for (int mi = 0; mi < 4; mi++) {
        int r0 = brow + warp_m * 64 + mi * 16 + (lane >> 2);
        float sx0 = g_sqx[r0];
        float sx1 = g_sqx[r0 + 8];
        #pragma unroll
        for (int ni = 0; ni < 8; ni++) {
            int cc = bcol + warp_n * 64 + ni * 8 + (lane & 3) * 2;
            float sy0 = g_sqy[cc], sy1 = g_sqy[cc + 1];
            __half2 h0 = __floats2half2_rn(fmaxf(sx0 + sy0 - 2.f * acc[mi][ni][0], 0.f),
                                           fmaxf(sx0 + sy1 - 2.f * acc[mi][ni][1], 0.f));
            __half2 h1 = __floats2half2_rn(fmaxf(sx1 + sy0 - 2.f * acc[mi][ni][2], 0.f),
                                           fmaxf(sx1 + sy1 - 2.f * acc[mi][ni][3], 0.f));
            *(__half2*)(g_C + (size_t)r0 * NN + cc)       = h0;
            *(__half2*)(g_C + (size_t)(r0 + 8) * NN + cc) = h1;
        }
    }
}

// ---------------- fallback: sum of row dot products (fp16 inputs) ---------
__global__ __launch_bounds__(128) void fallback_kernel() {
    int row = blockIdx.x;
    int tid = threadIdx.x;
    uint2 xr = ((const uint2*)(g_Xh + (size_t)row * DD))[tid];
    uint2 yr = ((const uint2*)(g_Yh + (size_t)row * DD))[tid];
    float2 x0 = __half22float2(*(__half2*)&xr.x), x1 = __half22float2(*(__half2*)&xr.y);
    float2 y0 = __half22float2(*(__half2*)&yr.x), y1 = __half22float2(*(__half2*)&yr.y);
    float d = x0.x*y0.x + x0.y*y0.y + x1.x*y1.x + x1.y*y1.y;
    __shared__ float red[4];
    #pragma unroll
    for (int o = 16; o > 0; o >>= 1) d += __shfl_xor_sync(0xffffffffu, d, o);
    if ((tid & 31) == 0) red[tid >> 5] = d;
    __syncthreads();
    if (tid == 0) atomicAdd(&g_fb, red[0] + red[1] + red[2] + red[3]);
}

// online LSE accumulate helper
__device__ __forceinline__ void lse_acc(float a, float& m, float& s) {
    if (a > m) { s = s * __expf(m - a) + 1.f; m = a; } else s += __expf(a - m);
}

// ---------------- row pass: log_u_i = -LSE_j(-5*C_ij + log_v_j) ------------
__global__ __launch_bounds__(256) void row_lse_kernel() {
    int row = blockIdx.x;
    int tid = threadIdx.x;
    const uint4* Cr = (const uint4*)(g_C + (size_t)row * NN);   // 8 halves each
    const float4* Lv = (const float4*)g_logv;

    float m = NEGBIG, s = 0.f;
    for (int c = tid; c < NN / 8; c += 256) {
        uint4 cv = Cr[c];
        float4 lv0 = Lv[2*c], lv1 = Lv[2*c + 1];
        float2 c0 = __half22float2(*(const __half2*)&cv.x);
        float2 c1 = __half22float2(*(const __half2*)&cv.y);
        float2 c2 = __half22float2(*(const __half2*)&cv.z);
        float2 c3 = __half22float2(*(const __half2*)&cv.w);
        lse_acc(fmaf(-EPS_INV, c0.x, lv0.x), m, s);
        lse_acc(fmaf(-EPS_INV, c0.y, lv0.y), m, s);
        lse_acc(fmaf(-EPS_INV, c1.x, lv0.z), m, s);
        lse_acc(fmaf(-EPS_INV, c1.y, lv0.w), m, s);
        lse_acc(fmaf(-EPS_INV, c2.x, lv1.x), m, s);
        lse_acc(fmaf(-EPS_INV, c2.y, lv1.y), m, s);
        lse_acc(fmaf(-EPS_INV, c3.x, lv1.z), m, s);
        lse_acc(fmaf(-EPS_INV, c3.y, lv1.w), m, s);
    }

    __shared__ float sm[256], ss[256];
    sm[tid] = m; ss[tid] = s;
    __syncthreads();
    for (int o = 128; o > 0; o >>= 1) {
        if (tid < o) {
            float m1 = sm[tid], s1 = ss[tid];
            float m2 = sm[tid + o], s2 = ss[tid + o];
            float M = fmaxf(m1, m2);
            sm[tid] = M;
            ss[tid] = s1 * __expf(m1 - M) + s2 * __expf(m2 - M);
        }
        __syncthreads();
    }
    if (tid == 0) g_logu[row] = -(sm[0] + logf(ss[0]));
}

// ------------- column pass, phase 1: per (row-chunk, column) partial LSE ---
__global__ __launch_bounds__(256) void col_partial_kernel() {
    int col = blockIdx.y * 256 + threadIdx.x;
    int r0  = blockIdx.x * 256;
    __shared__ float slu[256];
    slu[threadIdx.x] = g_logu[r0 + threadIdx.x];
    __syncthreads();

    float m = NEGBIG, s = 0.f;
    const __half* Cp = g_C + (size_t)r0 * NN + col;
    #pragma unroll 4
    for (int i = 0; i < 256; i++) {
        float a = fmaf(-EPS_INV, __half2float(Cp[(size_t)i * NN]), slu[i]);
        lse_acc(a, m, s);
    }
    g_cm[blockIdx.x * NN + col] = m;
    g_cs[blockIdx.x * NN + col] = s;
}

// ------------- column pass, phase 2: combine 32 partials per column --------
__global__ __launch_bounds__(256) void col_combine_kernel() {
    int col = blockIdx.x * 256 + threadIdx.x;
    float M = NEGBIG;
    #pragma unroll
    for (int ch = 0; ch < 32; ch++) M = fmaxf(M, g_cm[ch * NN + col]);
    float S = 0.f;
    #pragma unroll
    for (int ch = 0; ch < 32; ch++) S += g_cs[ch * NN + col] * __expf(g_cm[ch * NN + col] - M);
    g_logv[col] = -(M + logf(S));
}

// ------------- final: sum over all i,j of clip(exp(lu+lK+lv),0,1) * C ------
__global__ __launch_bounds__(256) void distance_kernel() {
    int row = blockIdx.x;
    int tid = threadIdx.x;
    float lu = g_logu[row];
    const uint4* Cr = (const uint4*)(g_C + (size_t)row * NN);
    const float4* Lv = (const float4*)g_logv;

    float sum = 0.f;
    for (int c = tid; c < NN / 8; c += 256) {
        uint4 cv = Cr[c];
        float4 lv0 = Lv[2*c], lv1 = Lv[2*c + 1];
        float2 c0 = __half22float2(*(const __half2*)&cv.x);
        float2 c1 = __half22float2(*(const __half2*)&cv.y);
        float2 c2 = __half22float2(*(const __half2*)&cv.z);
        float2 c3 = __half22float2(*(const __half2*)&cv.w);
        float p;
        p = fminf(__expf(fmaf(-EPS_INV, c0.x, lu + lv0.x)), 1.f); sum = fmaf(p, c0.x, sum);
        p = fminf(__expf(fmaf(-EPS_INV, c0.y, lu + lv0.y)), 1.f); sum = fmaf(p, c0.y, sum);
        p = fminf(__expf(fmaf(-EPS_INV, c1.x, lu + lv0.z)), 1.f); sum = fmaf(p, c1.x, sum);
        p = fminf(__expf(fmaf(-EPS_INV, c1.y, lu + lv0.w)), 1.f); sum = fmaf(p, c1.y, sum);
        p = fminf(__expf(fmaf(-EPS_INV, c2.x, lu + lv1.x)), 1.f); sum = fmaf(p, c2.x, sum);
        p = fminf(__expf(fmaf(-EPS_INV, c2.y, lu + lv1.y)), 1.f); sum = fmaf(p, c2.y, sum);
        p = fminf(__expf(fmaf(-EPS_INV, c3.x, lu + lv1.z)), 1.f); sum = fmaf(p, c3.x, sum);
        p = fminf(__expf(fmaf(-EPS_INV, c3.y, lu + lv1.w)), 1.f); sum = fmaf(p, c3.y, sum);
    }

    __shared__ float red[8];
    #pragma unroll
    for (int o = 16; o > 0; o >>= 1) sum += __shfl_xor_sync(0xffffffffu, sum, o);
    if ((tid & 31) == 0) red[tid >> 5] = sum;
    __syncthreads();
    if (tid == 0) {
        float b = 0.f;
        #pragma unroll
        for (int w = 0; w < 8; w++) b += red[w];
        atomicAdd(&g_accum, b);
    }
}

// ---------------- finalize ----------------
__global__ void finalize_kernel(float* out) {
    float d  = g_accum / (float)NN;
    float fb = 1.f - g_fb / (float)NN;
    out[0] = (isnan(d) || isinf(d)) ? fb : d;
}

// ---------------- launch ----------------
extern "C" void kernel_launch(void* const* d_in, const int* in_sizes, int n_in,
                              void* d_out, int out_size) {
    const float* emb = (const float*)d_in[0];
    const float* tn  = (const float*)d_in[1];
    float* out = (float*)d_out;

    cudaFuncSetAttribute(gemm_mma_kernel, cudaFuncAttributeMaxDynamicSharedMemorySize, GEMM_SMEM);

    init_kernel<<<32, 256>>>();
    normalize_kernel<<<2 * NN, 128>>>(emb, tn);
    gemm_mma_kernel<<<dim3(NN / BN, NN / BM), 128, GEMM_SMEM>>>();
    fallback_kernel<<<NN, 128>>>();

    for (int it = 0; it < 10; it++) {
        row_lse_kernel<<<NN, 256>>>();
        col_partial_kernel<<<dim3(32, 32), 256>>>();
        col_combine_kernel<<<32, 256>>>();
    }

    distance_kernel<<<NN, 256>>>();
    finalize_kernel<<<1, 1>>>(out);
}

// round 7
// speedup vs baseline: 3.2615x; 1.6973x over previous
#include <cuda_runtime.h>
#include <cuda_fp16.h>
#include <math.h>
#include <stdint.h>

// Problem constants
#define NN 8192
#define DD 512
#define QD (4.0f / 255.0f)       // dequant scale for C
#define QS 63.75f                // quant scale 255/4
#define LUTC (-20.0f / 255.0f)   // exp(-5 * C) = exp(LUTC * q)

// ---------------- device scratch (static: allocation rules) ----------------
__device__ __half g_Xh[NN * DD];            // normalized embeddings, fp16   8 MB
__device__ __half g_Yh[NN * DD];            // normalized target noise, fp16 8 MB
__device__ float g_sqx[NN];
__device__ float g_sqy[NN];
__device__ unsigned char g_Cq[(size_t)NN * (size_t)NN];  // quantized cost, 64 MB
__device__ float g_su[NN];                  // row sums  (eu = 1/su)
__device__ float g_ev[NN];                  // exp(log_v)
__device__ float g_cs[32 * NN];             // column partial sums
__device__ float g_tbl[256];                // LUT: exp(-20 q / 255)
__device__ float g_accum;                   // sum(P*q)
__device__ float g_fb;                      // sum of row dots (fallback)

// ---------------- helpers ----------------
__device__ __forceinline__ uint32_t smem_u32(const void* p) {
    uint32_t a;
    asm("{ .reg .u64 t; cvta.to.shared.u64 t, %1; cvt.u32.u64 %0, t; }" : "=r"(a) : "l"(p));
    return a;
}
__device__ __forceinline__ void cp_async16(uint32_t s, const void* g) {
    asm volatile("cp.async.cg.shared.global [%0], [%1], 16;" :: "r"(s), "l"(g));
}
#define CP_COMMIT()  asm volatile("cp.async.commit_group;" ::: "memory")
#define CP_WAIT(n)   asm volatile("cp.async.wait_group %0;" :: "n"(n) : "memory")

__device__ __forceinline__ void ldmatrix_x4(uint32_t& r0, uint32_t& r1, uint32_t& r2, uint32_t& r3,
                                            uint32_t addr) {
    asm volatile("ldmatrix.sync.aligned.m8n8.x4.shared.b16 {%0,%1,%2,%3}, [%4];"
                 : "=r"(r0), "=r"(r1), "=r"(r2), "=r"(r3) : "r"(addr));
}
__device__ __forceinline__ void mma_16816(float* c, const uint32_t* a, const uint32_t* b) {
    asm volatile("mma.sync.aligned.m16n8k16.row.col.f32.f16.f16.f32 "
                 "{%0,%1,%2,%3}, {%4,%5,%6,%7}, {%8,%9}, {%0,%1,%2,%3};"
                 : "+f"(c[0]), "+f"(c[1]), "+f"(c[2]), "+f"(c[3])
                 : "r"(a[0]), "r"(a[1]), "r"(a[2]), "r"(a[3]), "r"(b[0]), "r"(b[1]));
}

// ---------------- init ----------------
__global__ void init_kernel() {
    int i = blockIdx.x * blockDim.x + threadIdx.x;
    if (i < NN) g_ev[i] = 1.0f;
    if (i < 256) g_tbl[i] = expf(LUTC * (float)i);
    if (i == 0) { g_accum = 0.f; g_fb = 0.f; }
}

// ---------------- normalize: fp32 in -> fp16 normalized + sq --------------
__global__ __launch_bounds__(128) void normalize_kernel(const float* __restrict__ emb,
                                                        const float* __restrict__ tn) {
    int b = blockIdx.x;
    const float* src;
    __half* dst;
    float* sqv;
    int row;
    if (b < NN) { row = b;      src = emb + (size_t)row * DD; dst = g_Xh + (size_t)row * DD; sqv = g_sqx; }
    else        { row = b - NN; src = tn  + (size_t)row * DD; dst = g_Yh + (size_t)row * DD; sqv = g_sqy; }

    int tid = threadIdx.x;
    float4 v = ((const float4*)src)[tid];
    float ss = v.x*v.x + v.y*v.y + v.z*v.z + v.w*v.w;

    __shared__ float red[4];
    #pragma unroll
    for (int o = 16; o > 0; o >>= 1) ss += __shfl_xor_sync(0xffffffffu, ss, o);
    if ((tid & 31) == 0) red[tid >> 5] = ss;
    __syncthreads();
    float tot = red[0] + red[1] + red[2] + red[3];

    float norm = sqrtf(tot);
    float inv  = 1.0f / fmaxf(norm, 1e-12f);
    float4 w;
    w.x = v.x * inv; w.y = v.y * inv; w.z = v.z * inv; w.w = v.w * inv;

    __half2 h01 = __floats2half2_rn(w.x, w.y);
    __half2 h23 = __floats2half2_rn(w.z, w.w);
    *(uint2*)(dst + tid * 4) = make_uint2(*(uint32_t*)&h01, *(uint32_t*)&h23);

    float ss2 = w.x*w.x + w.y*w.y + w.z*w.z + w.w*w.w;
    #pragma unroll
    for (int o = 16; o > 0; o >>= 1) ss2 += __shfl_xor_sync(0xffffffffu, ss2, o);
    __syncthreads();
    if ((tid & 31) == 0) red[tid >> 5] = ss2;
    __syncthreads();
    if (tid == 0) sqv[row] = red[0] + red[1] + red[2] + red[3];
}

// ---------------- HMMA GEMM: Cq = quant(max(sqx_i + sqy_j - 2*dot, 0)) -----
#define BM 128
#define BN 128
#define BK 32
#define NITER (DD / BK)          // 16
#define SROW 40                  // smem row stride in halves (80 bytes)
#define STAGES 3
#define A_BYTES (BM * SROW * 2)
#define STAGE_BYTES (2 * A_BYTES)
#define GEMM_SMEM (STAGES * STAGE_BYTES)

__global__ __launch_bounds__(128, 2) void gemm_mma_kernel() {
    extern __shared__ __align__(16) char smem[];
    const int tid = threadIdx.x;
    const int wid = tid >> 5;
    const int lane = tid & 31;
    const int warp_m = wid >> 1;
    const int warp_n = wid & 1;
    const int brow = blockIdx.y * BM;
    const int bcol = blockIdx.x * BN;

    float acc[4][8][4];
    #pragma unroll
    for (int mi = 0; mi < 4; mi++)
        #pragma unroll
        for (int ni = 0; ni < 8; ni++)
            #pragma unroll
            for (int r = 0; r < 4; r++) acc[mi][ni][r] = 0.f;

    uint32_t sbase = smem_u32(smem);

    #pragma unroll
    for (int s = 0; s < STAGES - 1; s++) {
        int k0 = s * BK;
        uint32_t sa = sbase + s * STAGE_BYTES;
        uint32_t sb = sa + A_BYTES;
        #pragma unroll
        for (int i = 0; i < 4; i++) {
            int idx = i * 128 + tid;
            int r = idx >> 2, ch = idx & 3;
            cp_async16(sa + (uint32_t)(r * SROW + ch * 8) * 2, g_Xh + (size_t)(brow + r) * DD + k0 + ch * 8);
        }
        #pragma unroll
        for (int i = 0; i < 4; i++) {
            int idx = i * 128 + tid;
            int r = idx >> 2, ch = idx & 3;
            cp_async16(sb + (uint32_t)(r * SROW + ch * 8) * 2, g_Yh + (size_t)(bcol + r) * DD + k0 + ch * 8);
        }
        CP_COMMIT();
    }

    int buf = 0;
    for (int c = 0; c < NITER; c++) {
        CP_WAIT(STAGES - 2);
        __syncthreads();

        if (c + STAGES - 1 < NITER) {
            int ps = (c + STAGES - 1) % STAGES;
            int k0 = (c + STAGES - 1) * BK;
            uint32_t sa = sbase + ps * STAGE_BYTES;
            uint32_t sb = sa + A_BYTES;
            #pragma unroll
            for (int i = 0; i < 4; i++) {
                int idx = i * 128 + tid;
                int r = idx >> 2, ch = idx & 3;
                cp_async16(sa + (uint32_t)(r * SROW + ch * 8) * 2, g_Xh + (size_t)(brow + r) * DD + k0 + ch * 8);
            }
            #pragma unroll
            for (int i = 0; i < 4; i++) {
                int idx = i * 128 + tid;
                int r = idx >> 2, ch = idx & 3;
                cp_async16(sb + (uint32_t)(r * SROW + ch * 8) * 2, g_Yh + (size_t)(bcol + r) * DD + k0 + ch * 8);
            }
        }
        CP_COMMIT();

        uint32_t sa = sbase + buf * STAGE_BYTES;
        uint32_t sb = sa + A_BYTES;

        #pragma unroll
        for (int ks = 0; ks < 2; ks++) {
            uint32_t afr[4][4];
            #pragma unroll
            for (int mi = 0; mi < 4; mi++) {
                int row = warp_m * 64 + mi * 16 + (lane & 15);
                int col = ks * 16 + ((lane >> 4) << 3);
                ldmatrix_x4(afr[mi][0], afr[mi][1], afr[mi][2], afr[mi][3],
                            sa + (uint32_t)(row * SROW + col) * 2);
            }
            uint32_t bfr[8][2];
            #pragma unroll
            for (int np = 0; np < 4; np++) {
                int nrow = warp_n * 64 + np * 16 + ((lane >> 4) << 3) + (lane & 7);
                int col  = ks * 16 + (((lane >> 3) & 1) << 3);
                uint32_t r0, r1, r2, r3;
                ldmatrix_x4(r0, r1, r2, r3, sb + (uint32_t)(nrow * SROW + col) * 2);
                bfr[np*2][0] = r0; bfr[np*2][1] = r1;
                bfr[np*2+1][0] = r2; bfr[np*2+1][1] = r3;
            }
            #pragma unroll
            for (int mi = 0; mi < 4; mi++)
                #pragma unroll
                for (int ni = 0; ni < 8; ni++)
                    mma_16816(acc[mi][ni], afr[mi], bfr[ni]);
        }
        buf = (buf + 1 == STAGES) ? 0 : buf + 1;
    }

    // epilogue: quantize C = max(sqx + sqy - 2*dot, 0) to u8
    #pragma unroll
    for (int mi = 0; mi < 4; mi++) {
        int r0 = brow + warp_m * 64 + mi * 16 + (lane >> 2);
        float sx0 = g_sqx[r0];
        float sx1 = g_sqx[r0 + 8];
        #pragma unroll
        for (int ni = 0; ni < 8; ni++) {
            int cc = bcol + warp_n * 64 + ni * 8 + (lane & 3) * 2;
            float sy0 = g_sqy[cc], sy1 = g_sqy[cc + 1];
            uint32_t q00 = __float2uint_rn(fminf(fmaxf(sx0 + sy0 - 2.f * acc[mi][ni][0], 0.f) * QS, 255.f));
            uint32_t q01 = __float2uint_rn(fminf(fmaxf(sx0 + sy1 - 2.f * acc[mi][ni][1], 0.f) * QS, 255.f));
            uint32_t q10 = __float2uint_rn(fminf(fmaxf(sx1 + sy0 - 2.f * acc[mi][ni][2], 0.f) * QS, 255.f));
            uint32_t q11 = __float2uint_rn(fminf(fmaxf(sx1 + sy1 - 2.f * acc[mi][ni][3], 0.f) * QS, 255.f));
            *(unsigned short*)(g_Cq + (size_t)r0 * NN + cc)       = (unsigned short)(q00 | (q01 << 8));
            *(unsigned short*)(g_Cq + (size_t)(r0 + 8) * NN + cc) = (unsigned short)(q10 | (q11 << 8));
        }
    }
}

// ---------------- fallback: sum of row dot products (fp16 inputs) ---------
__global__ __launch_bounds__(128) void fallback_kernel() {
    int row = blockIdx.x;
    int tid = threadIdx.x;
    uint2 xr = ((const uint2*)(g_Xh + (size_t)row * DD))[tid];
    uint2 yr = ((const uint2*)(g_Yh + (size_t)row * DD))[tid];
    float2 x0 = __half22float2(*(__half2*)&xr.x), x1 = __half22float2(*(__half2*)&xr.y);
    float2 y0 = __half22float2(*(__half2*)&yr.x), y1 = __half22float2(*(__half2*)&yr.y);
    float d = x0.x*y0.x + x0.y*y0.y + x1.x*y1.x + x1.y*y1.y;
    __shared__ float red[4];
    #pragma unroll
    for (int o = 16; o > 0; o >>= 1) d += __shfl_xor_sync(0xffffffffu, d, o);
    if ((tid & 31) == 0) red[tid >> 5] = d;
    __syncthreads();
    if (tid == 0) atomicAdd(&g_fb, red[0] + red[1] + red[2] + red[3]);
}

// ---------------- row pass: su_i = sum_j LUT[q_ij] * ev_j ------------------
__global__ __launch_bounds__(256) void row_sum_kernel() {
    int row = blockIdx.x;
    int tid = threadIdx.x;
    __shared__ float tbl[256];
    tbl[tid] = g_tbl[tid];
    __syncthreads();

    const uint4* Cq = (const uint4*)(g_Cq + (size_t)row * NN);  // 512 chunks of 16 bytes
    const float4* Ev = (const float4*)g_ev;

    float s = 0.f;
    #pragma unroll
    for (int it = 0; it < 2; it++) {
        int c = it * 256 + tid;
        uint4 q = Cq[c];
        float4 e0 = Ev[4*c], e1 = Ev[4*c+1], e2 = Ev[4*c+2], e3 = Ev[4*c+3];
        s = fmaf(tbl[ q.x        & 255], e0.x, s);
        s = fmaf(tbl[(q.x >>  8) & 255], e0.y, s);
        s = fmaf(tbl[(q.x >> 16) & 255], e0.z, s);
        s = fmaf(tbl[(q.x >> 24)      ], e0.w, s);
        s = fmaf(tbl[ q.y        & 255], e1.x, s);
        s = fmaf(tbl[(q.y >>  8) & 255], e1.y, s);
        s = fmaf(tbl[(q.y >> 16) & 255], e1.z, s);
        s = fmaf(tbl[(q.y >> 24)      ], e1.w, s);
        s = fmaf(tbl[ q.z        & 255], e2.x, s);
        s = fmaf(tbl[(q.z >>  8) & 255], e2.y, s);
        s = fmaf(tbl[(q.z >> 16) & 255], e2.z, s);
        s = fmaf(tbl[(q.z >> 24)      ], e2.w, s);
        s = fmaf(tbl[ q.w        & 255], e3.x, s);
        s = fmaf(tbl[(q.w >>  8) & 255], e3.y, s);
        s = fmaf(tbl[(q.w >> 16) & 255], e3.z, s);
        s = fmaf(tbl[(q.w >> 24)      ], e3.w, s);
    }

    __shared__ float red[8];
    #pragma unroll
    for (int o = 16; o > 0; o >>= 1) s += __shfl_xor_sync(0xffffffffu, s, o);
    if ((tid & 31) == 0) red[tid >> 5] = s;
    __syncthreads();
    if (tid == 0) {
        float t = 0.f;
        #pragma unroll
        for (int w = 0; w < 8; w++) t += red[w];
        g_su[row] = t;
    }
}

// ------------- column pass, phase 1: partial sums over 256-row chunks ------
// grid (32 chunks, 8 col-blocks), 256 threads, 4 columns per thread.
__global__ __launch_bounds__(256) void col_partial_kernel() {
    int tid = threadIdx.x;
    int col = blockIdx.y * 1024 + tid * 4;
    int r0  = blockIdx.x * 256;

    __shared__ float tbl[256];
    __shared__ float seu[256];
    tbl[tid] = g_tbl[tid];
    seu[tid] = 1.0f / g_su[r0 + tid];     // eu = exp(log_u) = 1/su
    __syncthreads();

    float a0 = 0.f, a1 = 0.f, a2 = 0.f, a3 = 0.f;
    const unsigned char* Cp = g_Cq + (size_t)r0 * NN + col;
    #pragma unroll 4
    for (int i = 0; i < 256; i++) {
        uint32_t w = *(const uint32_t*)(Cp + (size_t)i * NN);
        float e = seu[i];
        a0 = fmaf(tbl[ w        & 255], e, a0);
        a1 = fmaf(tbl[(w >>  8) & 255], e, a1);
        a2 = fmaf(tbl[(w >> 16) & 255], e, a2);
        a3 = fmaf(tbl[(w >> 24)      ], e, a3);
    }
    *(float4*)(g_cs + blockIdx.x * NN + col) = make_float4(a0, a1, a2, a3);
}

// ------------- column pass, phase 2: combine 32 partials -> ev -------------
__global__ __launch_bounds__(256) void col_combine_kernel() {
    int col = blockIdx.x * 256 + threadIdx.x;
    float S = 0.f;
    #pragma unroll
    for (int ch = 0; ch < 32; ch++) S += g_cs[ch * NN + col];
    g_ev[col] = 1.0f / S;                 // ev = exp(log_v) = 1/S
}

// ------------- final: sum over i,j of min(eu*ev*K, 1) * q ------------------
__global__ __launch_bounds__(256) void distance_kernel() {
    int row = blockIdx.x;
    int tid = threadIdx.x;
    __shared__ float tbl[256];
    tbl[tid] = g_tbl[tid];
    __syncthreads();

    float eu = 1.0f / g_su[row];
    const uint4* Cq = (const uint4*)(g_Cq + (size_t)row * NN);
    const float4* Ev = (const float4*)g_ev;

    float sum = 0.f;
    #pragma unroll
    for (int it = 0; it < 2; it++) {
        int c = it * 256 + tid;
        uint4 q = Cq[c];
        float4 e0 = Ev[4*c], e1 = Ev[4*c+1], e2 = Ev[4*c+2], e3 = Ev[4*c+3];
        uint32_t b;
        float p;
        b =  q.x        & 255; p = fminf(eu * (e0.x * tbl[b]), 1.f); sum = fmaf(p, (float)b, sum);
        b = (q.x >>  8) & 255; p = fminf(eu * (e0.y * tbl[b]), 1.f); sum = fmaf(p, (float)b, sum);
        b = (q.x >> 16) & 255; p = fminf(eu * (e0.z * tbl[b]), 1.f); sum = fmaf(p, (float)b, sum);
        b = (q.x >> 24)      ; p = fminf(eu * (e0.w * tbl[b]), 1.f); sum = fmaf(p, (float)b, sum);
        b =  q.y        & 255; p = fminf(eu * (e1.x * tbl[b]), 1.f); sum = fmaf(p, (float)b, sum);
        b = (q.y >>  8) & 255; p = fminf(eu * (e1.y * tbl[b]), 1.f); sum = fmaf(p, (float)b, sum);
        b = (q.y >> 16) & 255; p = fminf(eu * (e1.z * tbl[b]), 1.f); sum = fmaf(p, (float)b, sum);
        b = (q.y >> 24)      ; p = fminf(eu * (e1.w * tbl[b]), 1.f); sum = fmaf(p, (float)b, sum);
        b =  q.z        & 255; p = fminf(eu * (e2.x * tbl[b]), 1.f); sum = fmaf(p, (float)b, sum);
        b = (q.z >>  8) & 255; p = fminf(eu * (e2.y * tbl[b]), 1.f); sum = fmaf(p, (float)b, sum);
        b = (q.z >> 16) & 255; p = fminf(eu * (e2.z * tbl[b]), 1.f); sum = fmaf(p, (float)b, sum);
        b = (q.z >> 24)      ; p = fminf(eu * (e2.w * tbl[b]), 1.f); sum = fmaf(p, (float)b, sum);
        b =  q.w        & 255; p = fminf(eu * (e3.x * tbl[b]), 1.f); sum = fmaf(p, (float)b, sum);
        b = (q.w >>  8) & 255; p = fminf(eu * (e3.y * tbl[b]), 1.f); sum = fmaf(p, (float)b, sum);
        b = (q.w >> 16) & 255; p = fminf(eu * (e3.z * tbl[b]), 1.f); sum = fmaf(p, (float)b, sum);
        b = (q.w >> 24)      ; p = fminf(eu * (e3.w * tbl[b]), 1.f); sum = fmaf(p, (float)b, sum);
    }

    __shared__ float red[8];
    #pragma unroll
    for (int o = 16; o > 0; o >>= 1) sum += __shfl_xor_sync(0xffffffffu, sum, o);
    if ((tid & 31) == 0) red[tid >> 5] = sum;
    __syncthreads();
    if (tid == 0) {
        float b = 0.f;
        #pragma unroll
        for (int w = 0; w < 8; w++) b += red[w];
        atomicAdd(&g_accum, b * QD);     // scale q -> C here
    }
}

// ---------------- finalize ----------------
__global__ void finalize_kernel(float* out) {
    float d  = g_accum / (float)NN;
    float fb = 1.f - g_fb / (float)NN;
    out[0] = (isnan(d) || isinf(d)) ? fb : d;
}

// ---------------- launch ----------------
extern "C" void kernel_launch(void* const* d_in, const int* in_sizes, int n_in,
                              void* d_out, int out_size) {
    const float* emb = (const float*)d_in[0];
    const float* tn  = (const float*)d_in[1];
    float* out = (float*)d_out;

    cudaFuncSetAttribute(gemm_mma_kernel, cudaFuncAttributeMaxDynamicSharedMemorySize, GEMM_SMEM);

    init_kernel<<<32, 256>>>();
    normalize_kernel<<<2 * NN, 128>>>(emb, tn);
    gemm_mma_kernel<<<dim3(NN / BN, NN / BM), 128, GEMM_SMEM>>>();
    fallback_kernel<<<NN, 128>>>();

    for (int it = 0; it < 10; it++) {
        row_sum_kernel<<<NN, 256>>>();
        col_partial_kernel<<<dim3(32, 8), 256>>>();
        col_combine_kernel<<<32, 256>>>();
    }

    distance_kernel<<<NN, 256>>>();
    finalize_kernel<<<1, 1>>>(out);
}